// round 11
// baseline (speedup 1.0000x reference)
#include <cuda_runtime.h>
#include <cuda_bf16.h>

#define NN 32768
#define BB 4
#define WW 512
#define FF 127
#define NFT (BB*FF)
#define TILE 4096
#define NEAR_LO 1792
#define NEAR_SPAN 4096
#define FCH 16            // frames per far-chunk
#define NCH 8             // far chunks
#define NCHK 64           // 512-wide argmax chunks per row

// ---- device scratch ----
__device__ unsigned long long d_amax[NFT];
__device__ unsigned long long d_ckey[NFT * NCHK];   // stage-1 per-chunk max keys
__device__ float d_Pc[NCH * BB * NN];
__device__ float d_ftab[NFT * 8];
__device__ double d_acc;

__device__ __forceinline__ float hamm(int j) {
    return 0.54f - 0.46f * cospif((float)j * (1.0f / 256.0f));
}

// order-preserving pack; ties -> smaller k wins (matches jnp.argmax)
__device__ __forceinline__ unsigned long long packkey(float v, unsigned k) {
    unsigned u = __float_as_uint(v);
    u = (u & 0x80000000u) ? ~u : (u | 0x80000000u);
    return ((unsigned long long)u << 32) | (0xFFFFFFFFu - k);
}
__device__ __forceinline__ float unpackval(unsigned long long key) {
    unsigned uv = (unsigned)(key >> 32);
    unsigned u = (uv & 0x80000000u) ? (uv & 0x7FFFFFFFu) : ~uv;
    return __uint_as_float(u);
}

__device__ __forceinline__ __nv_bfloat162 asb2(unsigned u) {
    return *reinterpret_cast<__nv_bfloat162*>(&u);
}
__device__ __forceinline__ unsigned asu32(__nv_bfloat162 v) {
    return *reinterpret_cast<unsigned*>(&v);
}

__global__ void k_init() {
    int i = blockIdx.x * blockDim.x + threadIdx.x;
    if (i < NFT) d_amax[i] = 0ull;
    if (i == NFT) d_acc = 0.0;
}

// ==== STAGE 1: bf16x2 conv (2 frames per lane-pair), per-chunk argmax keys ====
// csh[i] = dup-bf16(t[tile0-512+i]); wsh2[j] = (w_f0[j], w_f1[j]).
// Structure mirrors the proven R5 conv16 (X[24] sliding window, 8 taps/group).
__global__ __launch_bounds__(256, 2) void k_s1(const float* __restrict__ recon,
                                               const float* __restrict__ target) {
    __shared__ __align__(16) unsigned raw[4640];
    __shared__ __align__(16) unsigned wsh2[512];
    unsigned* csh = raw + 16;
    const int tid = threadIdx.x;
    const int tile0 = blockIdx.x * TILE;
    const int p = blockIdx.y, b = blockIdx.z;
    const int f0 = 2 * p, f1 = 2 * p + 1;
    const bool v1 = (f1 < FF);
    const float* tb = target + b * NN;

    for (int j = tid; j < 512; j += 256) {
        float w0 = hamm(j) * recon[b * NN + f0 * 256 + j];
        float w1 = v1 ? hamm(j) * recon[b * NN + f1 * 256 + j] : 0.0f;
        unsigned h0 = (unsigned)__bfloat16_as_ushort(__float2bfloat16(w0));
        unsigned h1 = (unsigned)__bfloat16_as_ushort(__float2bfloat16(w1));
        wsh2[j] = h0 | (h1 << 16);
    }
    for (int i = tid; i < 4624; i += 256) {
        int gi = tile0 - 528 + i;
        float v = (gi >= 0 && gi < NN) ? tb[gi] : 0.0f;
        unsigned h = (unsigned)__bfloat16_as_ushort(__float2bfloat16(v));
        raw[i] = h | (h << 16);
    }
    __syncthreads();

    unsigned X[24];
    const unsigned* base = csh + 16 * tid + 504;
#pragma unroll
    for (int i = 0; i < 6; i++) {
        uint4 v = *(const uint4*)(base + 4 * i);
        X[4*i+0]=v.x; X[4*i+1]=v.y; X[4*i+2]=v.z; X[4*i+3]=v.w;
    }

    float aflo[16], afhi[16];
#pragma unroll
    for (int t = 0; t < 16; t++) { aflo[t] = 0.f; afhi[t] = 0.f; }

#pragma unroll 2
    for (int seg = 0; seg < 16; seg++) {        // 16 segments x 32 taps
        unsigned acc2[16];
#pragma unroll
        for (int t = 0; t < 16; t++) acc2[t] = 0u;
#pragma unroll
        for (int g = 0; g < 4; g++) {
            const int j0 = seg * 32 + g * 8;
            uint4 w0 = *(const uint4*)(wsh2 + j0);
            uint4 w1 = *(const uint4*)(wsh2 + j0 + 4);
            unsigned wr[8] = {w0.x,w0.y,w0.z,w0.w,w1.x,w1.y,w1.z,w1.w};
#pragma unroll
            for (int c = 0; c < 8; c++)
#pragma unroll
                for (int t = 0; t < 16; t++)
                    acc2[t] = asu32(__hfma2(asb2(wr[c]), asb2(X[8 + t - c]), asb2(acc2[t])));
#pragma unroll
            for (int i = 23; i >= 8; i--) X[i] = X[i - 8];
            uint4 n0 = *(const uint4*)(base - j0 - 8);
            uint4 n1 = *(const uint4*)(base - j0 - 4);
            X[0]=n0.x; X[1]=n0.y; X[2]=n0.z; X[3]=n0.w;
            X[4]=n1.x; X[5]=n1.y; X[6]=n1.z; X[7]=n1.w;
        }
        // flush: bf16->fp32 exactly via bit ops
#pragma unroll
        for (int t = 0; t < 16; t++) {
            aflo[t] += __uint_as_float(acc2[t] << 16);
            afhi[t] += __uint_as_float(acc2[t] & 0xFFFF0000u);
        }
    }

    // per-warp (= per-512-chunk) argmax for each of the two frames
    const unsigned kb = (unsigned)(tile0 + 16 * tid);
    unsigned long long klo = packkey(aflo[0], kb);
    unsigned long long khi = packkey(afhi[0], kb);
#pragma unroll
    for (int t = 1; t < 16; t++) {
        unsigned long long a = packkey(aflo[t], kb + t); if (a > klo) klo = a;
        unsigned long long c = packkey(afhi[t], kb + t); if (c > khi) khi = c;
    }
#pragma unroll
    for (int s = 16; s > 0; s >>= 1) {
        unsigned long long a = __shfl_xor_sync(0xFFFFFFFFu, klo, s); if (a > klo) klo = a;
        unsigned long long c = __shfl_xor_sync(0xFFFFFFFFu, khi, s); if (c > khi) khi = c;
    }
    const int wid = tid >> 5;
    const int chunk = blockIdx.x * 8 + wid;
    if ((tid & 31) == 0) {
        d_ckey[(b * FF + f0) * NCHK + chunk] = klo;
        if (v1) d_ckey[(b * FF + f1) * NCHK + chunk] = khi;
    }
}

// ==== STAGE 2: exact fp32 recompute of candidate chunks -> d_amax ====
__global__ __launch_bounds__(128) void k_cand(const float* __restrict__ recon,
                                              const float* __restrict__ target) {
    __shared__ __align__(16) float wsh[512];
    __shared__ __align__(16) float xs[1024];
    __shared__ unsigned long long keys[NCHK];
    __shared__ unsigned long long wred[4];
    __shared__ int clist[NCHK];
    __shared__ int ncand;
    __shared__ float gthr;

    const int tid = threadIdx.x;
    const int f = blockIdx.x, b = blockIdx.y;
    const int bf = b * FF + f;
    const float* tb = target + b * NN;
    const float* rb = recon + b * NN + f * 256;

    for (int j = tid; j < 512; j += 128) wsh[j] = hamm(j) * rb[j];
    if (tid < NCHK) keys[tid] = d_ckey[bf * NCHK + tid];
    __syncthreads();

    if (tid == 0) {
        unsigned long long g = keys[0];
        for (int c = 1; c < NCHK; c++) if (keys[c] > g) g = keys[c];
        gthr = unpackval(g) - 3.0f;
        int n = 0;
        for (int c = 0; c < NCHK; c++)
            if (unpackval(keys[c]) >= gthr) clist[n++] = c;
        ncand = n;
    }
    __syncthreads();

    const int nc = ncand;
    for (int ci = 0; ci < nc; ci++) {
        const int k0 = clist[ci] * 512;
        __syncthreads();
        for (int i = tid; i < 1024; i += 128) {
            int gi = k0 - 512 + i;
            xs[i] = (gi >= 0) ? tb[gi] : 0.0f;
        }
        __syncthreads();

        float acc[4] = {0.f, 0.f, 0.f, 0.f};
        const float* xb = xs + 512 + 4 * tid;
#pragma unroll 4
        for (int j0 = 0; j0 < 512; j0 += 8) {
            float4 w0 = *(const float4*)(wsh + j0);
            float4 w1 = *(const float4*)(wsh + j0 + 4);
            float wr[8] = {w0.x,w0.y,w0.z,w0.w,w1.x,w1.y,w1.z,w1.w};
            float Y[12];
            const float* pp = xb - j0 - 8;
#pragma unroll
            for (int q = 0; q < 3; q++) {
                float4 v = *(const float4*)(pp + 4 * q);
                Y[4*q+0]=v.x; Y[4*q+1]=v.y; Y[4*q+2]=v.z; Y[4*q+3]=v.w;
            }
#pragma unroll
            for (int c = 0; c < 8; c++)
#pragma unroll
                for (int q = 0; q < 4; q++)
                    acc[q] = fmaf(wr[c], Y[8 - c + q], acc[q]);
        }

        unsigned kb = (unsigned)(k0 + 4 * tid);
        unsigned long long key = packkey(acc[0], kb);
#pragma unroll
        for (int q = 1; q < 4; q++) {
            unsigned long long kq = packkey(acc[q], kb + q);
            if (kq > key) key = kq;
        }
#pragma unroll
        for (int s = 16; s > 0; s >>= 1) {
            unsigned long long o = __shfl_xor_sync(0xFFFFFFFFu, key, s);
            if (o > key) key = o;
        }
        if ((tid & 31) == 0) wred[tid >> 5] = key;
        __syncthreads();
        if (tid == 0) {
            unsigned long long m = wred[0];
            if (wred[1] > m) m = wred[1];
            if (wred[2] > m) m = wred[2];
            if (wred[3] > m) m = wred[3];
            atomicMax(&d_amax[bf], m);
        }
    }
}

// ---- per-frame params + moments for the far-field expansion ----
__global__ void k_prep(const float* __restrict__ recon) {
    __shared__ float4 red[128];
    const int bf = blockIdx.x;
    const int b = bf / FF, f = bf % FF;
    const int tid = threadIdx.x;
    const unsigned a = 0xFFFFFFFFu - (unsigned)(d_amax[bf] & 0xFFFFFFFFull);
    const bool delta = (a == 0u);
    const float r = (float)a * (1.0f / 32769.0f);
    const float beta = delta ? 1.0f
        : ((a & 1u) ? -1.0f : 1.0f) * sinpif(r) * (1.0f / 65536.0f);
    const float* rb = recon + b * NN + f * 256;

    float m0 = 0.f, m1 = 0.f, m2 = 0.f, m3 = 0.f;
#pragma unroll
    for (int q = 0; q < 4; q++) {
        int j = tid * 4 + q;
        float s = (j & 1) ? -1.0f : 1.0f;
        float g = beta * s * hamm(j) * rb[j];
        float tau = (255.5f - (float)j) * (1.0f / 256.0f);
        float t2 = tau * tau;
        m0 += g; m1 += g * tau; m2 += g * t2; m3 += g * t2 * tau;
    }
    red[tid] = make_float4(m0, m1, m2, m3);
    __syncthreads();
    for (int s = 64; s > 0; s >>= 1) {
        if (tid < s) {
            float4 x = red[tid], y = red[tid + s];
            red[tid] = make_float4(x.x+y.x, x.y+y.y, x.z+y.z, x.w+y.w);
        }
        __syncthreads();
    }
    if (tid == 0) {
        float* e = d_ftab + bf * 8;
        float4 m = red[0];
        e[0] = __int_as_float((int)a);
        e[1] = r;
        e[2] = m.x; e[3] = m.y; e[4] = m.z; e[5] = m.w;
    }
}

// ---- far-field: cubic cot-Taylor x moments; frame-chunked for occupancy ----
__global__ __launch_bounds__(256) void k_far() {
    __shared__ float ft[FCH * 8];
    const int tid = threadIdx.x;
    const int chunk = blockIdx.y, b = blockIdx.z;
    const int f0 = chunk * FCH;
    const int nf = (f0 + FCH < FF) ? FCH : (FF - f0);
    for (int i = tid; i < nf * 8; i += 256) ft[i] = d_ftab[(b * FF + f0) * 8 + i];
    __syncthreads();

    const int m0i = blockIdx.x * 1024 + tid * 4;
    float F[4] = {0.f, 0.f, 0.f, 0.f};
    const float G = 0.01227184630f;   // pi/256

    for (int f = 0; f < nf; f++) {
        const float* e = ft + f * 8;
        int a = __float_as_int(e[0]);
        if (a == 0) continue;
        float r = e[1], M0 = e[2], M1 = e[3], M2 = e[4], M3 = e[5];
        float dbase = (float)(m0i - a) + (r - 255.5f);
        int rel = m0i - (a - NEAR_LO);
#pragma unroll
        for (int k = 0; k < 4; k++) {
            if ((unsigned)(rel + k) < (unsigned)NEAR_SPAN) continue;
            float u = (dbase + (float)k) * (1.0f / 65536.0f);
            float c0 = __fdividef(cospif(u), sinpif(u));
            float c2 = c0 * c0;
            float q = c2 + 1.0f;
            float t = fmaf(G, fmaf(G, (c2 + 0.33333333f) * M3, -c0 * M2), M1);
            F[k] = fmaf(c0, M0, fmaf(-G * q, t, F[k]));
        }
    }
    float4 outv = make_float4(F[0], -F[1], F[2], -F[3]);
    *(float4*)(d_Pc + ((size_t)(chunk * BB + b)) * NN + m0i) = outv;
}

// Register-sliding-window 512-tap fp32 conv (proven R5 structure)
__device__ __forceinline__ void conv16(const float* __restrict__ csh,
                                       const float* __restrict__ wsh,
                                       int tid, float* __restrict__ acc) {
    float X[24];
    const float* base = csh + 16 * tid + 504;
#pragma unroll
    for (int i = 0; i < 6; i++) {
        float4 v = *(const float4*)(base + 4 * i);
        X[4*i+0]=v.x; X[4*i+1]=v.y; X[4*i+2]=v.z; X[4*i+3]=v.w;
    }
#pragma unroll 8
    for (int j0 = 0; j0 < 512; j0 += 8) {
        float4 w0 = *(const float4*)(wsh + j0);
        float4 w1 = *(const float4*)(wsh + j0 + 4);
        float wr[8] = {w0.x,w0.y,w0.z,w0.w,w1.x,w1.y,w1.z,w1.w};
#pragma unroll
        for (int c = 0; c < 8; c++)
#pragma unroll
            for (int t = 0; t < 16; t++)
                acc[t] = fmaf(wr[c], X[8 + t - c], acc[t]);
#pragma unroll
        for (int i = 23; i >= 8; i--) X[i] = X[i - 8];
        float4 n0 = *(const float4*)(base - j0 - 8);
        float4 n1 = *(const float4*)(base - j0 - 4);
        X[0]=n0.x; X[1]=n0.y; X[2]=n0.z; X[3]=n0.w;
        X[4]=n1.x; X[5]=n1.y; X[6]=n1.z; X[7]=n1.w;
    }
}

// ---- near-field: exact 512-tap conv, 2 blocks x 2048 outputs per frame ----
__global__ __launch_bounds__(128, 4) void k_near(const float* __restrict__ recon) {
    __shared__ __align__(16) float raw[2592];
    __shared__ __align__(16) float wsh[512];
    float* csh = raw + 8;
    const int tid = threadIdx.x;
    const int f = blockIdx.y, b = blockIdx.z;
    const int bf = b * FF + f;
    const unsigned a = 0xFFFFFFFFu - (unsigned)(d_amax[bf] & 0xFFFFFFFFull);
    const int tile0 = (int)a - NEAR_LO + blockIdx.x * 2048;
    if (tile0 >= NN || tile0 + 2048 <= 0) return;
    const bool delta = (a == 0u);
    const float r = (float)a * (1.0f / 32769.0f);
    const float beta = delta ? 1.0f
        : ((a & 1u) ? -1.0f : 1.0f) * sinpif(r) * (1.0f / 65536.0f);
    const float* rb = recon + b * NN + f * 256;

    for (int j = tid; j < 512; j += 128) {
        float s = (j & 1) ? -1.0f : 1.0f;
        wsh[j] = beta * s * hamm(j) * rb[j];
    }
    for (int i = tid; i < 2592; i += 128) {
        int d = tile0 - 520 + i;
        float v;
        if (delta) {
            v = (d == 0) ? 1.0f : 0.0f;
        } else if (d < -511) {
            v = 0.0f;
        } else {
            float u = ((float)(d - (int)a) + r) * (1.0f / 65536.0f);
            v = __fdividef(cospif(u), sinpif(u));
        }
        raw[i] = v;
    }
    __syncthreads();

    float acc[16];
#pragma unroll
    for (int t = 0; t < 16; t++) acc[t] = 0.0f;
    conv16(csh, wsh, tid, acc);

    const int mb = tile0 + 16 * tid;
    float* Pb = d_Pc + b * NN;
#pragma unroll
    for (int t = 0; t < 16; t++) {
        int m = mb + t;
        if ((unsigned)m < (unsigned)NN) {
            float val = (m & 1) ? -acc[t] : acc[t];
            atomicAdd(Pb + m, val);
        }
    }
}

// ---- parallel MSE reduction ----
__global__ void k_loss(const float* __restrict__ target) {
    __shared__ double red[256];
    const int tid = threadIdx.x;
    double s = 0.0;
    for (int i = blockIdx.x * 256 + tid; i < BB * NN; i += gridDim.x * 256) {
        int b = i >> 15, m = i & (NN - 1);
        float p = 0.f;
#pragma unroll
        for (int c = 0; c < NCH; c++)
            p += d_Pc[((size_t)(c * BB + b)) * NN + m];
        double dd = (double)p - (double)target[i];
        s += dd * dd;
    }
    red[tid] = s;
    __syncthreads();
    for (int st = 128; st > 0; st >>= 1) {
        if (tid < st) red[tid] += red[tid + st];
        __syncthreads();
    }
    if (tid == 0) atomicAdd(&d_acc, red[0]);
}

__global__ void k_final(float* __restrict__ out) {
    out[0] = (float)(d_acc / (double)(BB * NN));
}

extern "C" void kernel_launch(void* const* d_in, const int* in_sizes, int n_in,
                              void* d_out, int out_size) {
    const float* recon  = (const float*)d_in[0];
    const float* target = (const float*)d_in[1];
    float* out = (float*)d_out;
    (void)in_sizes; (void)n_in; (void)out_size;

    k_init<<<2, 256>>>();
    k_s1<<<dim3(NN / TILE, 64, BB), 256>>>(recon, target);
    k_cand<<<dim3(FF, BB), 128>>>(recon, target);
    k_prep<<<NFT, 128>>>(recon);
    k_far<<<dim3(NN / 1024, NCH, BB), 256>>>();
    k_near<<<dim3(2, FF, BB), 128>>>(recon);
    k_loss<<<128, 256>>>(target);
    k_final<<<1, 1>>>(out);
}

// round 12
// speedup vs baseline: 2.4763x; 2.4763x over previous
#include <cuda_runtime.h>
#include <cuda_bf16.h>

#define NN 32768
#define BB 4
#define WW 512
#define FF 127
#define NFT (BB*FF)
#define NEAR_LO 1792
#define NEAR_SPAN 4096
#define FCH 16            // frames per far-chunk
#define NCH 8             // far chunks
#define NCHK2 256         // 128-wide argmax chunks per row

// ---- device scratch ----
__device__ unsigned long long d_amax[NFT];
__device__ unsigned long long d_ckey[NFT * NCHK2];   // stage-1 per-chunk max keys
__device__ unsigned d_wbf[BB * 128 * 256];           // bf16x2-packed weights [b][n][512]
__device__ float d_Pc[NCH * BB * NN];
__device__ float d_ftab[NFT * 8];
__device__ double d_acc;

__device__ __forceinline__ float hamm(int j) {
    return 0.54f - 0.46f * cospif((float)j * (1.0f / 256.0f));
}

// order-preserving pack; ties -> smaller k wins (matches jnp.argmax)
__device__ __forceinline__ unsigned long long packkey(float v, unsigned k) {
    unsigned u = __float_as_uint(v);
    u = (u & 0x80000000u) ? ~u : (u | 0x80000000u);
    return ((unsigned long long)u << 32) | (0xFFFFFFFFu - k);
}
__device__ __forceinline__ float unpackval(unsigned long long key) {
    unsigned uv = (unsigned)(key >> 32);
    unsigned u = (uv & 0x80000000u) ? (uv & 0x7FFFFFFFu) : ~uv;
    return __uint_as_float(u);
}

__global__ void k_init() {
    int i = blockIdx.x * blockDim.x + threadIdx.x;
    if (i < NFT) d_amax[i] = 0ull;
    if (i == NFT) d_acc = 0.0;
}

// ---- weight prep: bf16 w[f][j] = hamm(j)*recon, packed 2/u32, rows padded to 128 ----
__global__ __launch_bounds__(128) void k_wprep(const float* __restrict__ recon) {
    const int bn = blockIdx.x;            // b*128 + n
    const int b = bn >> 7, n = bn & 127;
    const int tid = threadIdx.x;
    const int j = tid * 4;
    float w0 = 0.f, w1 = 0.f, w2 = 0.f, w3 = 0.f;
    if (n < FF) {
        const float* rb = recon + b * NN + n * 256;
        w0 = hamm(j) * rb[j];     w1 = hamm(j+1) * rb[j+1];
        w2 = hamm(j+2) * rb[j+2]; w3 = hamm(j+3) * rb[j+3];
    }
    unsigned lo = (unsigned)__bfloat16_as_ushort(__float2bfloat16(w0))
                | ((unsigned)__bfloat16_as_ushort(__float2bfloat16(w1)) << 16);
    unsigned hi = (unsigned)__bfloat16_as_ushort(__float2bfloat16(w2))
                | ((unsigned)__bfloat16_as_ushort(__float2bfloat16(w3)) << 16);
    unsigned* dst = d_wbf + bn * 256 + tid * 2;
    dst[0] = lo; dst[1] = hi;
}

// ==== STAGE 1: tensor-core conv1 via mma.sync m16n8k16 bf16 ====
// CTA = (tile of 128 kpos, batch). D[m=kpos_local, n=frame] = sum_j w[n][j]*t[k0+m-j].
// A[m][kk] = trev[127-m+kk] (Toeplitz), B[n][kk] = w (col operand, k-contiguous).
__global__ __launch_bounds__(256) void k_s1t(const float* __restrict__ target) {
    __shared__ unsigned short trev[640];
    __shared__ __align__(16) unsigned wch[1024];      // 128 rows x 8 u32 (16 bf16)
    __shared__ unsigned long long red[8 * 128];
    const int tid = threadIdx.x;
    const int wid = tid >> 5, lid = tid & 31;
    const int g = lid >> 2, tg = lid & 3;
    const int tile = blockIdx.x, b = blockIdx.y;
    const int k0 = tile * 128;
    const float* tb = target + b * NN;

    for (int i = tid; i < 640; i += 256) {
        int gi = k0 + 127 - i;
        float v = (gi >= 0) ? tb[gi] : 0.0f;
        trev[i] = __bfloat16_as_ushort(__float2bfloat16(v));
    }

    float d[64];
#pragma unroll
    for (int i = 0; i < 64; i++) d[i] = 0.0f;

    const int nrow = tid >> 1, nh = tid & 1;
    const unsigned* wsrc = d_wbf + (b * 128 + nrow) * 256 + nh * 4;
    unsigned* wdst = wch + nrow * 8 + nh * 4;
    const int m0 = 16 * wid + g;

    for (int kc = 0; kc < 32; kc++) {
        __syncthreads();
        *(uint4*)wdst = *(const uint4*)(wsrc + kc * 8);
        __syncthreads();
        const int i0 = 127 - m0 + kc * 16 + tg * 2;
        unsigned a0 = (unsigned)trev[i0]     | ((unsigned)trev[i0 + 1] << 16);
        unsigned a1 = (unsigned)trev[i0 - 8] | ((unsigned)trev[i0 - 7] << 16);
        unsigned a2 = (unsigned)trev[i0 + 8] | ((unsigned)trev[i0 + 9] << 16);
        unsigned a3 = a0;   // Toeplitz: row+8, col+8 -> same data
#pragma unroll
        for (int nt = 0; nt < 16; nt++) {
            unsigned b0 = wch[(nt * 8 + g) * 8 + tg];
            unsigned b1 = wch[(nt * 8 + g) * 8 + tg + 4];
            asm volatile(
                "mma.sync.aligned.m16n8k16.row.col.f32.bf16.bf16.f32 "
                "{%0,%1,%2,%3}, {%4,%5,%6,%7}, {%8,%9}, {%0,%1,%2,%3};"
                : "+f"(d[nt*4+0]), "+f"(d[nt*4+1]), "+f"(d[nt*4+2]), "+f"(d[nt*4+3])
                : "r"(a0), "r"(a1), "r"(a2), "r"(a3), "r"(b0), "r"(b1));
        }
    }

    // epilogue: lane holds rows m0, m0+8; cols tg*2, tg*2+1 per 8-wide n-tile
    const unsigned mk = (unsigned)(k0 + m0);
#pragma unroll
    for (int nt = 0; nt < 16; nt++) {
        unsigned long long key0 = packkey(d[nt*4+0], mk);
        unsigned long long u2 = packkey(d[nt*4+2], mk + 8); if (u2 > key0) key0 = u2;
        unsigned long long key1 = packkey(d[nt*4+1], mk);
        unsigned long long u3 = packkey(d[nt*4+3], mk + 8); if (u3 > key1) key1 = u3;
#pragma unroll
        for (int s = 4; s <= 16; s <<= 1) {     // reduce over g (lane bits 2..4)
            unsigned long long o0 = __shfl_xor_sync(0xFFFFFFFFu, key0, s); if (o0 > key0) key0 = o0;
            unsigned long long o1 = __shfl_xor_sync(0xFFFFFFFFu, key1, s); if (o1 > key1) key1 = o1;
        }
        if (lid < 4) {                          // lid == tg here
            red[wid * 128 + nt * 8 + lid * 2]     = key0;
            red[wid * 128 + nt * 8 + lid * 2 + 1] = key1;
        }
    }
    __syncthreads();
    if (tid < 128) {
        unsigned long long m = red[tid];
#pragma unroll
        for (int w = 1; w < 8; w++) {
            unsigned long long o = red[w * 128 + tid];
            if (o > m) m = o;
        }
        if (tid < FF) d_ckey[(b * FF + tid) * NCHK2 + tile] = m;
    }
}

// ==== STAGE 2: exact fp32 recompute of candidate 128-chunks (bit-identical chain) ====
__global__ __launch_bounds__(128) void k_cand(const float* __restrict__ recon,
                                              const float* __restrict__ target) {
    __shared__ __align__(16) float wsh[512];
    __shared__ float xs[640];
    __shared__ unsigned long long keys[NCHK2];
    __shared__ unsigned long long wred[4];
    __shared__ short clist[NCHK2];
    __shared__ int ncand;
    const int tid = threadIdx.x;
    const int f = blockIdx.x, b = blockIdx.y;
    const int bf = b * FF + f;
    const float* tb = target + b * NN;
    const float* rb = recon + b * NN + f * 256;

    for (int j = tid; j < 512; j += 128) wsh[j] = hamm(j) * rb[j];
    for (int i = tid; i < NCHK2; i += 128) keys[i] = d_ckey[bf * NCHK2 + i];
    __syncthreads();

    if (tid == 0) {
        unsigned long long gk = keys[0];
        for (int c = 1; c < NCHK2; c++) if (keys[c] > gk) gk = keys[c];
        float thr = unpackval(gk) - 3.0f;       // > 2x deterministic bf16 error bound
        int n = 0;
        for (int c = 0; c < NCHK2; c++)
            if (unpackval(keys[c]) >= thr) clist[n++] = (short)c;
        ncand = n;
    }
    __syncthreads();

    const int nc = ncand;
    for (int ci = 0; ci < nc; ci++) {
        const int k0 = (int)clist[ci] * 128;
        __syncthreads();
        for (int i = tid; i < 640; i += 128) {
            int gi = k0 - 512 + i;
            xs[i] = (gi >= 0) ? tb[gi] : 0.0f;
        }
        __syncthreads();
        float acc = 0.0f;
        const float* xp = xs + tid + 512;
#pragma unroll 8
        for (int j0 = 0; j0 < 512; j0 += 4) {   // j ascending, one fma per j: exact chain
            float4 wv = *(const float4*)(wsh + j0);
            acc = fmaf(wv.x, xp[-j0], acc);
            acc = fmaf(wv.y, xp[-j0 - 1], acc);
            acc = fmaf(wv.z, xp[-j0 - 2], acc);
            acc = fmaf(wv.w, xp[-j0 - 3], acc);
        }
        unsigned long long key = packkey(acc, (unsigned)(k0 + tid));
#pragma unroll
        for (int s = 16; s > 0; s >>= 1) {
            unsigned long long o = __shfl_xor_sync(0xFFFFFFFFu, key, s);
            if (o > key) key = o;
        }
        if ((tid & 31) == 0) wred[tid >> 5] = key;
        __syncthreads();
        if (tid == 0) {
            unsigned long long m = wred[0];
            if (wred[1] > m) m = wred[1];
            if (wred[2] > m) m = wred[2];
            if (wred[3] > m) m = wred[3];
            atomicMax(&d_amax[bf], m);
        }
    }
}

// ---- per-frame params + moments for the far-field expansion ----
__global__ void k_prep(const float* __restrict__ recon) {
    __shared__ float4 red[128];
    const int bf = blockIdx.x;
    const int b = bf / FF, f = bf % FF;
    const int tid = threadIdx.x;
    const unsigned a = 0xFFFFFFFFu - (unsigned)(d_amax[bf] & 0xFFFFFFFFull);
    const bool delta = (a == 0u);
    const float r = (float)a * (1.0f / 32769.0f);
    const float beta = delta ? 1.0f
        : ((a & 1u) ? -1.0f : 1.0f) * sinpif(r) * (1.0f / 65536.0f);
    const float* rb = recon + b * NN + f * 256;

    float m0 = 0.f, m1 = 0.f, m2 = 0.f, m3 = 0.f;
#pragma unroll
    for (int q = 0; q < 4; q++) {
        int j = tid * 4 + q;
        float s = (j & 1) ? -1.0f : 1.0f;
        float g = beta * s * hamm(j) * rb[j];
        float tau = (255.5f - (float)j) * (1.0f / 256.0f);
        float t2 = tau * tau;
        m0 += g; m1 += g * tau; m2 += g * t2; m3 += g * t2 * tau;
    }
    red[tid] = make_float4(m0, m1, m2, m3);
    __syncthreads();
    for (int s = 64; s > 0; s >>= 1) {
        if (tid < s) {
            float4 x = red[tid], y = red[tid + s];
            red[tid] = make_float4(x.x+y.x, x.y+y.y, x.z+y.z, x.w+y.w);
        }
        __syncthreads();
    }
    if (tid == 0) {
        float* e = d_ftab + bf * 8;
        float4 m = red[0];
        e[0] = __int_as_float((int)a);
        e[1] = r;
        e[2] = m.x; e[3] = m.y; e[4] = m.z; e[5] = m.w;
    }
}

// ---- far-field: cubic cot-Taylor x moments; frame-chunked for occupancy ----
__global__ __launch_bounds__(256) void k_far() {
    __shared__ float ft[FCH * 8];
    const int tid = threadIdx.x;
    const int chunk = blockIdx.y, b = blockIdx.z;
    const int f0 = chunk * FCH;
    const int nf = (f0 + FCH < FF) ? FCH : (FF - f0);
    for (int i = tid; i < nf * 8; i += 256) ft[i] = d_ftab[(b * FF + f0) * 8 + i];
    __syncthreads();

    const int m0i = blockIdx.x * 1024 + tid * 4;
    float F[4] = {0.f, 0.f, 0.f, 0.f};
    const float G = 0.01227184630f;   // pi/256

    for (int f = 0; f < nf; f++) {
        const float* e = ft + f * 8;
        int a = __float_as_int(e[0]);
        if (a == 0) continue;
        float r = e[1], M0 = e[2], M1 = e[3], M2 = e[4], M3 = e[5];
        float dbase = (float)(m0i - a) + (r - 255.5f);
        int rel = m0i - (a - NEAR_LO);
#pragma unroll
        for (int k = 0; k < 4; k++) {
            if ((unsigned)(rel + k) < (unsigned)NEAR_SPAN) continue;
            float u = (dbase + (float)k) * (1.0f / 65536.0f);
            float c0 = __fdividef(cospif(u), sinpif(u));
            float c2 = c0 * c0;
            float q = c2 + 1.0f;
            float t = fmaf(G, fmaf(G, (c2 + 0.33333333f) * M3, -c0 * M2), M1);
            F[k] = fmaf(c0, M0, fmaf(-G * q, t, F[k]));
        }
    }
    float4 outv = make_float4(F[0], -F[1], F[2], -F[3]);
    *(float4*)(d_Pc + ((size_t)(chunk * BB + b)) * NN + m0i) = outv;
}

// Register-sliding-window 512-tap fp32 conv (proven R5 structure)
__device__ __forceinline__ void conv16(const float* __restrict__ csh,
                                       const float* __restrict__ wsh,
                                       int tid, float* __restrict__ acc) {
    float X[24];
    const float* base = csh + 16 * tid + 504;
#pragma unroll
    for (int i = 0; i < 6; i++) {
        float4 v = *(const float4*)(base + 4 * i);
        X[4*i+0]=v.x; X[4*i+1]=v.y; X[4*i+2]=v.z; X[4*i+3]=v.w;
    }
#pragma unroll 8
    for (int j0 = 0; j0 < 512; j0 += 8) {
        float4 w0 = *(const float4*)(wsh + j0);
        float4 w1 = *(const float4*)(wsh + j0 + 4);
        float wr[8] = {w0.x,w0.y,w0.z,w0.w,w1.x,w1.y,w1.z,w1.w};
#pragma unroll
        for (int c = 0; c < 8; c++)
#pragma unroll
            for (int t = 0; t < 16; t++)
                acc[t] = fmaf(wr[c], X[8 + t - c], acc[t]);
#pragma unroll
        for (int i = 23; i >= 8; i--) X[i] = X[i - 8];
        float4 n0 = *(const float4*)(base - j0 - 8);
        float4 n1 = *(const float4*)(base - j0 - 4);
        X[0]=n0.x; X[1]=n0.y; X[2]=n0.z; X[3]=n0.w;
        X[4]=n1.x; X[5]=n1.y; X[6]=n1.z; X[7]=n1.w;
    }
}

// ---- near-field: exact 512-tap conv, 2 blocks x 2048 outputs per frame ----
__global__ __launch_bounds__(128, 4) void k_near(const float* __restrict__ recon) {
    __shared__ __align__(16) float raw[2592];
    __shared__ __align__(16) float wsh[512];
    float* csh = raw + 8;
    const int tid = threadIdx.x;
    const int f = blockIdx.y, b = blockIdx.z;
    const int bf = b * FF + f;
    const unsigned a = 0xFFFFFFFFu - (unsigned)(d_amax[bf] & 0xFFFFFFFFull);
    const int tile0 = (int)a - NEAR_LO + blockIdx.x * 2048;
    if (tile0 >= NN || tile0 + 2048 <= 0) return;
    const bool delta = (a == 0u);
    const float r = (float)a * (1.0f / 32769.0f);
    const float beta = delta ? 1.0f
        : ((a & 1u) ? -1.0f : 1.0f) * sinpif(r) * (1.0f / 65536.0f);
    const float* rb = recon + b * NN + f * 256;

    for (int j = tid; j < 512; j += 128) {
        float s = (j & 1) ? -1.0f : 1.0f;
        wsh[j] = beta * s * hamm(j) * rb[j];
    }
    for (int i = tid; i < 2592; i += 128) {
        int d = tile0 - 520 + i;
        float v;
        if (delta) {
            v = (d == 0) ? 1.0f : 0.0f;
        } else if (d < -511) {
            v = 0.0f;
        } else {
            float u = ((float)(d - (int)a) + r) * (1.0f / 65536.0f);
            v = __fdividef(cospif(u), sinpif(u));
        }
        raw[i] = v;
    }
    __syncthreads();

    float acc[16];
#pragma unroll
    for (int t = 0; t < 16; t++) acc[t] = 0.0f;
    conv16(csh, wsh, tid, acc);

    const int mb = tile0 + 16 * tid;
    float* Pb = d_Pc + b * NN;
#pragma unroll
    for (int t = 0; t < 16; t++) {
        int m = mb + t;
        if ((unsigned)m < (unsigned)NN) {
            float val = (m & 1) ? -acc[t] : acc[t];
            atomicAdd(Pb + m, val);
        }
    }
}

// ---- parallel MSE reduction ----
__global__ void k_loss(const float* __restrict__ target) {
    __shared__ double red[256];
    const int tid = threadIdx.x;
    double s = 0.0;
    for (int i = blockIdx.x * 256 + tid; i < BB * NN; i += gridDim.x * 256) {
        int b = i >> 15, m = i & (NN - 1);
        float p = 0.f;
#pragma unroll
        for (int c = 0; c < NCH; c++)
            p += d_Pc[((size_t)(c * BB + b)) * NN + m];
        double dd = (double)p - (double)target[i];
        s += dd * dd;
    }
    red[tid] = s;
    __syncthreads();
    for (int st = 128; st > 0; st >>= 1) {
        if (tid < st) red[tid] += red[tid + st];
        __syncthreads();
    }
    if (tid == 0) atomicAdd(&d_acc, red[0]);
}

__global__ void k_final(float* __restrict__ out) {
    out[0] = (float)(d_acc / (double)(BB * NN));
}

extern "C" void kernel_launch(void* const* d_in, const int* in_sizes, int n_in,
                              void* d_out, int out_size) {
    const float* recon  = (const float*)d_in[0];
    const float* target = (const float*)d_in[1];
    float* out = (float*)d_out;
    (void)in_sizes; (void)n_in; (void)out_size;

    k_init<<<2, 256>>>();
    k_wprep<<<BB * 128, 128>>>(recon);
    k_s1t<<<dim3(NN / 128, BB), 256>>>(target);
    k_cand<<<dim3(FF, BB), 128>>>(recon, target);
    k_prep<<<NFT, 128>>>(recon);
    k_far<<<dim3(NN / 1024, NCH, BB), 256>>>();
    k_near<<<dim3(2, FF, BB), 128>>>(recon);
    k_loss<<<128, 256>>>(target);
    k_final<<<1, 1>>>(out);
}

// round 13
// speedup vs baseline: 2.8692x; 1.1587x over previous
#include <cuda_runtime.h>
#include <cuda_bf16.h>

#define NN 32768
#define BB 4
#define WW 512
#define FF 127
#define NFT (BB*FF)
#define NEAR_LO 1792
#define NEAR_SPAN 4096
#define FCH 16            // frames per far-chunk
#define NCH 8             // far chunks
#define NCHK2 256         // 128-wide argmax chunks per row
#define MAXJOBS (NFT * NCHK2)

// ---- device scratch ----
__device__ unsigned long long d_amax[NFT];
__device__ unsigned long long d_ckey[NFT * NCHK2];   // stage-1 per-chunk max keys
__device__ unsigned d_wbf[BB * 128 * 256];           // bf16x2-packed weights [b][n][512]
__device__ unsigned d_jobs[MAXJOBS];
__device__ int d_njobs;
__device__ float d_Pc[NCH * BB * NN];
__device__ float d_ftab[NFT * 8];
__device__ double d_acc;

__device__ __forceinline__ float hamm(int j) {
    return 0.54f - 0.46f * cospif((float)j * (1.0f / 256.0f));
}

// order-preserving pack; ties -> smaller k wins (matches jnp.argmax)
__device__ __forceinline__ unsigned long long packkey(float v, unsigned k) {
    unsigned u = __float_as_uint(v);
    u = (u & 0x80000000u) ? ~u : (u | 0x80000000u);
    return ((unsigned long long)u << 32) | (0xFFFFFFFFu - k);
}
__device__ __forceinline__ float unpackval(unsigned long long key) {
    unsigned uv = (unsigned)(key >> 32);
    unsigned u = (uv & 0x80000000u) ? (uv & 0x7FFFFFFFu) : ~uv;
    return __uint_as_float(u);
}

__global__ void k_init() {
    int i = blockIdx.x * blockDim.x + threadIdx.x;
    if (i < NFT) d_amax[i] = 0ull;
    if (i == NFT) d_acc = 0.0;
    if (i == NFT + 1) d_njobs = 0;
}

// ---- weight prep: bf16 w[f][j] = hamm(j)*recon, packed 2/u32, rows padded to 128 ----
__global__ __launch_bounds__(128) void k_wprep(const float* __restrict__ recon) {
    const int bn = blockIdx.x;            // b*128 + n
    const int b = bn >> 7, n = bn & 127;
    const int tid = threadIdx.x;
    const int j = tid * 4;
    float w0 = 0.f, w1 = 0.f, w2 = 0.f, w3 = 0.f;
    if (n < FF) {
        const float* rb = recon + b * NN + n * 256;
        w0 = hamm(j) * rb[j];     w1 = hamm(j+1) * rb[j+1];
        w2 = hamm(j+2) * rb[j+2]; w3 = hamm(j+3) * rb[j+3];
    }
    unsigned lo = (unsigned)__bfloat16_as_ushort(__float2bfloat16(w0))
                | ((unsigned)__bfloat16_as_ushort(__float2bfloat16(w1)) << 16);
    unsigned hi = (unsigned)__bfloat16_as_ushort(__float2bfloat16(w2))
                | ((unsigned)__bfloat16_as_ushort(__float2bfloat16(w3)) << 16);
    unsigned* dst = d_wbf + bn * 256 + tid * 2;
    dst[0] = lo; dst[1] = hi;
}

// ==== STAGE 1: tensor-core conv1 via mma.sync m16n8k16 bf16 ====
// CTA = (tile of 128 kpos, batch). D[m=kpos_local, n=frame] = sum_j w[n][j]*t[k0+m-j].
// A[m][kk] = trev[127-m+kk] (Toeplitz), B[n][kk] = w. Double-buffered B chunks.
__global__ __launch_bounds__(256) void k_s1t(const float* __restrict__ target) {
    __shared__ unsigned short trev[640];
    __shared__ __align__(16) unsigned wch[2][1024];   // 128 rows x 8 u32 (16 bf16)
    __shared__ unsigned long long red[8 * 128];
    const int tid = threadIdx.x;
    const int wid = tid >> 5, lid = tid & 31;
    const int g = lid >> 2, tg = lid & 3;
    const int tile = blockIdx.x, b = blockIdx.y;
    const int k0 = tile * 128;
    const float* tb = target + b * NN;

    for (int i = tid; i < 640; i += 256) {
        int gi = k0 + 127 - i;
        float v = (gi >= 0) ? tb[gi] : 0.0f;
        trev[i] = __bfloat16_as_ushort(__float2bfloat16(v));
    }

    float d[64];
#pragma unroll
    for (int i = 0; i < 64; i++) d[i] = 0.0f;

    const int nrow = tid >> 1, nh = tid & 1;
    const unsigned* wsrc = d_wbf + (b * 128 + nrow) * 256 + nh * 4;
    unsigned* wdst0 = wch[0] + nrow * 8 + nh * 4;
    unsigned* wdst1 = wch[1] + nrow * 8 + nh * 4;
    const int m0 = 16 * wid + g;

    *(uint4*)wdst0 = *(const uint4*)(wsrc);
    __syncthreads();

    for (int kc = 0; kc < 32; kc++) {
        // prefetch next chunk into the other buffer
        if (kc + 1 < 32) {
            unsigned* wd = (kc & 1) ? wdst0 : wdst1;
            *(uint4*)wd = *(const uint4*)(wsrc + (kc + 1) * 8);
        }
        const unsigned* wc = wch[kc & 1];
        const int i0 = 127 - m0 + kc * 16 + tg * 2;
        unsigned a0 = (unsigned)trev[i0]     | ((unsigned)trev[i0 + 1] << 16);
        unsigned a1 = (unsigned)trev[i0 - 8] | ((unsigned)trev[i0 - 7] << 16);
        unsigned a2 = (unsigned)trev[i0 + 8] | ((unsigned)trev[i0 + 9] << 16);
        unsigned a3 = a0;   // Toeplitz: row+8, col+8 -> same data
#pragma unroll
        for (int nt = 0; nt < 16; nt++) {
            unsigned b0 = wc[(nt * 8 + g) * 8 + tg];
            unsigned b1 = wc[(nt * 8 + g) * 8 + tg + 4];
            asm volatile(
                "mma.sync.aligned.m16n8k16.row.col.f32.bf16.bf16.f32 "
                "{%0,%1,%2,%3}, {%4,%5,%6,%7}, {%8,%9}, {%0,%1,%2,%3};"
                : "+f"(d[nt*4+0]), "+f"(d[nt*4+1]), "+f"(d[nt*4+2]), "+f"(d[nt*4+3])
                : "r"(a0), "r"(a1), "r"(a2), "r"(a3), "r"(b0), "r"(b1));
        }
        __syncthreads();
    }

    // epilogue: lane holds rows m0, m0+8; cols tg*2, tg*2+1 per 8-wide n-tile
    const unsigned mk = (unsigned)(k0 + m0);
#pragma unroll
    for (int nt = 0; nt < 16; nt++) {
        unsigned long long key0 = packkey(d[nt*4+0], mk);
        unsigned long long u2 = packkey(d[nt*4+2], mk + 8); if (u2 > key0) key0 = u2;
        unsigned long long key1 = packkey(d[nt*4+1], mk);
        unsigned long long u3 = packkey(d[nt*4+3], mk + 8); if (u3 > key1) key1 = u3;
#pragma unroll
        for (int s = 4; s <= 16; s <<= 1) {     // reduce over g (lane bits 2..4)
            unsigned long long o0 = __shfl_xor_sync(0xFFFFFFFFu, key0, s); if (o0 > key0) key0 = o0;
            unsigned long long o1 = __shfl_xor_sync(0xFFFFFFFFu, key1, s); if (o1 > key1) key1 = o1;
        }
        if (lid < 4) {                          // lid == tg here
            red[wid * 128 + nt * 8 + lid * 2]     = key0;
            red[wid * 128 + nt * 8 + lid * 2 + 1] = key1;
        }
    }
    __syncthreads();
    if (tid < 128) {
        unsigned long long m = red[tid];
#pragma unroll
        for (int w = 1; w < 8; w++) {
            unsigned long long o = red[w * 128 + tid];
            if (o > m) m = o;
        }
        if (tid < FF) d_ckey[(b * FF + tid) * NCHK2 + tile] = m;
    }
}

// ==== candidate selection: per frame, emit chunks within 3.0 of gmax ====
__global__ __launch_bounds__(256) void k_csel() {
    __shared__ unsigned long long keys[NCHK2];
    __shared__ float thr;
    const int tid = threadIdx.x;
    const int bf = blockIdx.x;
    keys[tid] = d_ckey[bf * NCHK2 + tid];
    __syncthreads();
    if (tid == 0) {
        unsigned long long g = keys[0];
        for (int c = 1; c < NCHK2; c++) if (keys[c] > g) g = keys[c];
        thr = unpackval(g) - 3.0f;   // > 2x deterministic bf16 error bound
    }
    __syncthreads();
    if (unpackval(keys[tid]) >= thr) {
        int pos = atomicAdd(&d_njobs, 1);
        d_jobs[pos] = (unsigned)(bf * NCHK2 + tid);
    }
}

// ==== STAGE 2: exact fp32 recompute, one block per candidate chunk ====
__global__ __launch_bounds__(128) void k_cand2(const float* __restrict__ recon,
                                               const float* __restrict__ target) {
    __shared__ __align__(16) float wsh[512];
    __shared__ float xs[640];
    __shared__ unsigned long long wred[4];
    const int tid = threadIdx.x;
    const int njobs = d_njobs;

    for (int ji = blockIdx.x; ji < njobs; ji += gridDim.x) {
        const unsigned v = d_jobs[ji];
        const int bf = (int)(v >> 8), chunk = (int)(v & 255u);
        const int b = bf / FF, f = bf % FF;
        const int k0 = chunk * 128;
        const float* tb = target + b * NN;
        const float* rb = recon + b * NN + f * 256;

        __syncthreads();   // protect smem reuse across jobs
        for (int j = tid; j < 512; j += 128) wsh[j] = hamm(j) * rb[j];
        for (int i = tid; i < 640; i += 128) {
            int gi = k0 - 512 + i;
            xs[i] = (gi >= 0) ? tb[gi] : 0.0f;
        }
        __syncthreads();

        float acc = 0.0f;
        const float* xp = xs + tid + 512;
#pragma unroll 8
        for (int j0 = 0; j0 < 512; j0 += 4) {   // j ascending, one fma per j: exact chain
            float4 wv = *(const float4*)(wsh + j0);
            acc = fmaf(wv.x, xp[-j0], acc);
            acc = fmaf(wv.y, xp[-j0 - 1], acc);
            acc = fmaf(wv.z, xp[-j0 - 2], acc);
            acc = fmaf(wv.w, xp[-j0 - 3], acc);
        }
        unsigned long long key = packkey(acc, (unsigned)(k0 + tid));
#pragma unroll
        for (int s = 16; s > 0; s >>= 1) {
            unsigned long long o = __shfl_xor_sync(0xFFFFFFFFu, key, s);
            if (o > key) key = o;
        }
        if ((tid & 31) == 0) wred[tid >> 5] = key;
        __syncthreads();
        if (tid == 0) {
            unsigned long long m = wred[0];
            if (wred[1] > m) m = wred[1];
            if (wred[2] > m) m = wred[2];
            if (wred[3] > m) m = wred[3];
            atomicMax(&d_amax[bf], m);
        }
    }
}

// ---- per-frame params + moments for the far-field expansion ----
__global__ void k_prep(const float* __restrict__ recon) {
    __shared__ float4 red[128];
    const int bf = blockIdx.x;
    const int b = bf / FF, f = bf % FF;
    const int tid = threadIdx.x;
    const unsigned a = 0xFFFFFFFFu - (unsigned)(d_amax[bf] & 0xFFFFFFFFull);
    const bool delta = (a == 0u);
    const float r = (float)a * (1.0f / 32769.0f);
    const float beta = delta ? 1.0f
        : ((a & 1u) ? -1.0f : 1.0f) * sinpif(r) * (1.0f / 65536.0f);
    const float* rb = recon + b * NN + f * 256;

    float m0 = 0.f, m1 = 0.f, m2 = 0.f, m3 = 0.f;
#pragma unroll
    for (int q = 0; q < 4; q++) {
        int j = tid * 4 + q;
        float s = (j & 1) ? -1.0f : 1.0f;
        float g = beta * s * hamm(j) * rb[j];
        float tau = (255.5f - (float)j) * (1.0f / 256.0f);
        float t2 = tau * tau;
        m0 += g; m1 += g * tau; m2 += g * t2; m3 += g * t2 * tau;
    }
    red[tid] = make_float4(m0, m1, m2, m3);
    __syncthreads();
    for (int s = 64; s > 0; s >>= 1) {
        if (tid < s) {
            float4 x = red[tid], y = red[tid + s];
            red[tid] = make_float4(x.x+y.x, x.y+y.y, x.z+y.z, x.w+y.w);
        }
        __syncthreads();
    }
    if (tid == 0) {
        float* e = d_ftab + bf * 8;
        float4 m = red[0];
        e[0] = __int_as_float((int)a);
        e[1] = r;
        e[2] = m.x; e[3] = m.y; e[4] = m.z; e[5] = m.w;
    }
}

// ---- far-field: cubic cot-Taylor x moments; frame-chunked for occupancy ----
__global__ __launch_bounds__(256) void k_far() {
    __shared__ float ft[FCH * 8];
    const int tid = threadIdx.x;
    const int chunk = blockIdx.y, b = blockIdx.z;
    const int f0 = chunk * FCH;
    const int nf = (f0 + FCH < FF) ? FCH : (FF - f0);
    for (int i = tid; i < nf * 8; i += 256) ft[i] = d_ftab[(b * FF + f0) * 8 + i];
    __syncthreads();

    const int m0i = blockIdx.x * 1024 + tid * 4;
    float F[4] = {0.f, 0.f, 0.f, 0.f};
    const float G = 0.01227184630f;   // pi/256

    for (int f = 0; f < nf; f++) {
        const float* e = ft + f * 8;
        int a = __float_as_int(e[0]);
        if (a == 0) continue;
        float r = e[1], M0 = e[2], M1 = e[3], M2 = e[4], M3 = e[5];
        float dbase = (float)(m0i - a) + (r - 255.5f);
        int rel = m0i - (a - NEAR_LO);
#pragma unroll
        for (int k = 0; k < 4; k++) {
            if ((unsigned)(rel + k) < (unsigned)NEAR_SPAN) continue;
            float u = (dbase + (float)k) * (1.0f / 65536.0f);
            float c0 = __fdividef(cospif(u), sinpif(u));
            float c2 = c0 * c0;
            float q = c2 + 1.0f;
            float t = fmaf(G, fmaf(G, (c2 + 0.33333333f) * M3, -c0 * M2), M1);
            F[k] = fmaf(c0, M0, fmaf(-G * q, t, F[k]));
        }
    }
    float4 outv = make_float4(F[0], -F[1], F[2], -F[3]);
    *(float4*)(d_Pc + ((size_t)(chunk * BB + b)) * NN + m0i) = outv;
}

// Register-sliding-window 512-tap fp32 conv (proven R5 structure)
__device__ __forceinline__ void conv16(const float* __restrict__ csh,
                                       const float* __restrict__ wsh,
                                       int tid, float* __restrict__ acc) {
    float X[24];
    const float* base = csh + 16 * tid + 504;
#pragma unroll
    for (int i = 0; i < 6; i++) {
        float4 v = *(const float4*)(base + 4 * i);
        X[4*i+0]=v.x; X[4*i+1]=v.y; X[4*i+2]=v.z; X[4*i+3]=v.w;
    }
#pragma unroll 8
    for (int j0 = 0; j0 < 512; j0 += 8) {
        float4 w0 = *(const float4*)(wsh + j0);
        float4 w1 = *(const float4*)(wsh + j0 + 4);
        float wr[8] = {w0.x,w0.y,w0.z,w0.w,w1.x,w1.y,w1.z,w1.w};
#pragma unroll
        for (int c = 0; c < 8; c++)
#pragma unroll
            for (int t = 0; t < 16; t++)
                acc[t] = fmaf(wr[c], X[8 + t - c], acc[t]);
#pragma unroll
        for (int i = 23; i >= 8; i--) X[i] = X[i - 8];
        float4 n0 = *(const float4*)(base - j0 - 8);
        float4 n1 = *(const float4*)(base - j0 - 4);
        X[0]=n0.x; X[1]=n0.y; X[2]=n0.z; X[3]=n0.w;
        X[4]=n1.x; X[5]=n1.y; X[6]=n1.z; X[7]=n1.w;
    }
}

// ---- near-field: exact 512-tap conv, 2 blocks x 2048 outputs per frame ----
__global__ __launch_bounds__(128, 4) void k_near(const float* __restrict__ recon) {
    __shared__ __align__(16) float raw[2592];
    __shared__ __align__(16) float wsh[512];
    float* csh = raw + 8;
    const int tid = threadIdx.x;
    const int f = blockIdx.y, b = blockIdx.z;
    const int bf = b * FF + f;
    const unsigned a = 0xFFFFFFFFu - (unsigned)(d_amax[bf] & 0xFFFFFFFFull);
    const int tile0 = (int)a - NEAR_LO + blockIdx.x * 2048;
    if (tile0 >= NN || tile0 + 2048 <= 0) return;
    const bool delta = (a == 0u);
    const float r = (float)a * (1.0f / 32769.0f);
    const float beta = delta ? 1.0f
        : ((a & 1u) ? -1.0f : 1.0f) * sinpif(r) * (1.0f / 65536.0f);
    const float* rb = recon + b * NN + f * 256;

    for (int j = tid; j < 512; j += 128) {
        float s = (j & 1) ? -1.0f : 1.0f;
        wsh[j] = beta * s * hamm(j) * rb[j];
    }
    for (int i = tid; i < 2592; i += 128) {
        int d = tile0 - 520 + i;
        float v;
        if (delta) {
            v = (d == 0) ? 1.0f : 0.0f;
        } else if (d < -511) {
            v = 0.0f;
        } else {
            float u = ((float)(d - (int)a) + r) * (1.0f / 65536.0f);
            v = __fdividef(cospif(u), sinpif(u));
        }
        raw[i] = v;
    }
    __syncthreads();

    float acc[16];
#pragma unroll
    for (int t = 0; t < 16; t++) acc[t] = 0.0f;
    conv16(csh, wsh, tid, acc);

    const int mb = tile0 + 16 * tid;
    float* Pb = d_Pc + b * NN;
#pragma unroll
    for (int t = 0; t < 16; t++) {
        int m = mb + t;
        if ((unsigned)m < (unsigned)NN) {
            float val = (m & 1) ? -acc[t] : acc[t];
            atomicAdd(Pb + m, val);
        }
    }
}

// ---- parallel MSE reduction ----
__global__ void k_loss(const float* __restrict__ target) {
    __shared__ double red[256];
    const int tid = threadIdx.x;
    double s = 0.0;
    for (int i = blockIdx.x * 256 + tid; i < BB * NN; i += gridDim.x * 256) {
        int b = i >> 15, m = i & (NN - 1);
        float p = 0.f;
#pragma unroll
        for (int c = 0; c < NCH; c++)
            p += d_Pc[((size_t)(c * BB + b)) * NN + m];
        double dd = (double)p - (double)target[i];
        s += dd * dd;
    }
    red[tid] = s;
    __syncthreads();
    for (int st = 128; st > 0; st >>= 1) {
        if (tid < st) red[tid] += red[tid + st];
        __syncthreads();
    }
    if (tid == 0) atomicAdd(&d_acc, red[0]);
}

__global__ void k_final(float* __restrict__ out) {
    out[0] = (float)(d_acc / (double)(BB * NN));
}

extern "C" void kernel_launch(void* const* d_in, const int* in_sizes, int n_in,
                              void* d_out, int out_size) {
    const float* recon  = (const float*)d_in[0];
    const float* target = (const float*)d_in[1];
    float* out = (float*)d_out;
    (void)in_sizes; (void)n_in; (void)out_size;

    k_init<<<2, 256>>>();
    k_wprep<<<BB * 128, 128>>>(recon);
    k_s1t<<<dim3(NN / 128, BB), 256>>>(target);
    k_csel<<<NFT, 256>>>();
    k_cand2<<<1024, 128>>>(recon, target);
    k_prep<<<NFT, 128>>>(recon);
    k_far<<<dim3(NN / 1024, NCH, BB), 256>>>();
    k_near<<<dim3(2, FF, BB), 128>>>(recon);
    k_loss<<<128, 256>>>(target);
    k_final<<<1, 1>>>(out);
}

// round 14
// speedup vs baseline: 3.4033x; 1.1861x over previous
#include <cuda_runtime.h>
#include <cuda_bf16.h>

#define NN 32768
#define BB 4
#define WW 512
#define FF 127
#define NFT (BB*FF)
#define NEAR_LO 1792
#define NEAR_SPAN 4096
#define FCH 16            // frames per far-chunk
#define NCH 8             // far chunks
#define NCHK2 256         // 128-wide argmax chunks per row
#define MAXJOBS (NFT * NCHK2)

// ---- device scratch ----
__device__ unsigned long long d_amax[NFT];
__device__ unsigned long long d_ckey[NFT * NCHK2];   // stage-1 per-chunk max keys
__device__ unsigned d_wbf[BB * 32 * 1024];           // fragment-ordered bf16 weights
__device__ unsigned d_jobs[MAXJOBS];
__device__ int d_njobs;
__device__ float d_Pc[NCH * BB * NN];
__device__ float d_ftab[NFT * 8];
__device__ double d_acc;

__device__ __forceinline__ float hamm(int j) {
    return 0.54f - 0.46f * cospif((float)j * (1.0f / 256.0f));
}

// order-preserving pack; ties -> smaller k wins (matches jnp.argmax)
__device__ __forceinline__ unsigned long long packkey(float v, unsigned k) {
    unsigned u = __float_as_uint(v);
    u = (u & 0x80000000u) ? ~u : (u | 0x80000000u);
    return ((unsigned long long)u << 32) | (0xFFFFFFFFu - k);
}
__device__ __forceinline__ float unpackval(unsigned long long key) {
    unsigned uv = (unsigned)(key >> 32);
    unsigned u = (uv & 0x80000000u) ? (uv & 0x7FFFFFFFu) : ~uv;
    return __uint_as_float(u);
}

// ---- weight prep (fragment-ordered, swizzled) + global init ----
// value u32 ku (0..255) of frame-row n: kc=ku>>3, cc=ku&7 -> tg=cc&3, half=cc>>2.
// class c = g*4+tg with g=n&7; nt=n>>3, p=nt>>1, s=(nt&1)*2+half.
// flat u32 = ((b*32+kc)*32 + c)*32 + ((p+c)&7)*4 + s.
__global__ __launch_bounds__(128) void k_wprep(const float* __restrict__ recon) {
    const int bn = blockIdx.x;            // b*128 + n
    const int b = bn >> 7, n = bn & 127;
    const int tid = threadIdx.x;

    if (bn == 0) {                        // fold former k_init
        for (int i = tid; i < NFT; i += 128) d_amax[i] = 0ull;
        if (tid == 0) { d_acc = 0.0; d_njobs = 0; }
    }

    const int j = tid * 4;
    float w0 = 0.f, w1 = 0.f, w2 = 0.f, w3 = 0.f;
    if (n < FF) {
        const float* rb = recon + b * NN + n * 256;
        w0 = hamm(j) * rb[j];     w1 = hamm(j+1) * rb[j+1];
        w2 = hamm(j+2) * rb[j+2]; w3 = hamm(j+3) * rb[j+3];
    }
    unsigned lo = (unsigned)__bfloat16_as_ushort(__float2bfloat16(w0))
                | ((unsigned)__bfloat16_as_ushort(__float2bfloat16(w1)) << 16);
    unsigned hi = (unsigned)__bfloat16_as_ushort(__float2bfloat16(w2))
                | ((unsigned)__bfloat16_as_ushort(__float2bfloat16(w3)) << 16);

    const int g = n & 7, nt = n >> 3, p = nt >> 1;
    const int sbase = (nt & 1) * 2;
#pragma unroll
    for (int q = 0; q < 2; q++) {
        const int ku = tid * 2 + q;
        const int kc = ku >> 3, cc = ku & 7;
        const int tg = cc & 3, half = cc >> 2;
        const int c = g * 4 + tg;
        const int flat = (((b * 32 + kc) * 32 + c) * 32) + (((p + c) & 7) * 4) + sbase + half;
        d_wbf[flat] = q ? hi : lo;
    }
}

// ==== STAGE 1: tensor-core conv1 via mma.sync m16n8k16 bf16 ====
// CTA = (tile of 128 kpos, batch). D[m=kpos_local, n=frame] = sum_j w[n][j]*t[k0+m-j].
// A[m][kk] = trev[127-m+kk] (Toeplitz). B fragment-ordered: class c = lid,
// uint4 @ c*32 + ((p+c)&7)*4 = {b0,b1} for nt=2p and nt=2p+1.
__global__ __launch_bounds__(256) void k_s1t(const float* __restrict__ target) {
    __shared__ unsigned short trev[640];
    __shared__ __align__(16) unsigned wch[2][1024];
    __shared__ unsigned long long red[8 * 128];
    const int tid = threadIdx.x;
    const int wid = tid >> 5, lid = tid & 31;
    const int g = lid >> 2, tg = lid & 3;
    const int tile = blockIdx.x, b = blockIdx.y;
    const int k0 = tile * 128;
    const float* tb = target + b * NN;

    for (int i = tid; i < 640; i += 256) {
        int gi = k0 + 127 - i;
        float v = (gi >= 0) ? tb[gi] : 0.0f;
        trev[i] = __bfloat16_as_ushort(__float2bfloat16(v));
    }

    float d[64];
#pragma unroll
    for (int i = 0; i < 64; i++) d[i] = 0.0f;

    const unsigned* wsrc = d_wbf + (b * 32) * 1024 + tid * 4;
    unsigned* wd[2] = { wch[0] + tid * 4, wch[1] + tid * 4 };
    const int m0 = 16 * wid + g;

    *(uint4*)wd[0] = *(const uint4*)(wsrc);     // kc = 0
    __syncthreads();

    for (int kc = 0; kc < 32; kc++) {
        uint4 pref;
        if (kc + 1 < 32) pref = *(const uint4*)(wsrc + (kc + 1) * 1024);  // LDG early

        const unsigned* wc = wch[kc & 1] + lid * 32;
        const int i0 = 127 - m0 + kc * 16 + tg * 2;
        unsigned a0 = (unsigned)trev[i0]     | ((unsigned)trev[i0 + 1] << 16);
        unsigned a1 = (unsigned)trev[i0 - 8] | ((unsigned)trev[i0 - 7] << 16);
        unsigned a2 = (unsigned)trev[i0 + 8] | ((unsigned)trev[i0 + 9] << 16);
        unsigned a3 = a0;   // Toeplitz: row+8, col+8 -> same data
#pragma unroll
        for (int p = 0; p < 8; p++) {
            uint4 bv = *(const uint4*)(wc + (((p + lid) & 7) << 2));
            float* d0 = d + (2 * p) * 4;
            float* d1 = d + (2 * p + 1) * 4;
            asm volatile(
                "mma.sync.aligned.m16n8k16.row.col.f32.bf16.bf16.f32 "
                "{%0,%1,%2,%3}, {%4,%5,%6,%7}, {%8,%9}, {%0,%1,%2,%3};"
                : "+f"(d0[0]), "+f"(d0[1]), "+f"(d0[2]), "+f"(d0[3])
                : "r"(a0), "r"(a1), "r"(a2), "r"(a3), "r"(bv.x), "r"(bv.y));
            asm volatile(
                "mma.sync.aligned.m16n8k16.row.col.f32.bf16.bf16.f32 "
                "{%0,%1,%2,%3}, {%4,%5,%6,%7}, {%8,%9}, {%0,%1,%2,%3};"
                : "+f"(d1[0]), "+f"(d1[1]), "+f"(d1[2]), "+f"(d1[3])
                : "r"(a0), "r"(a1), "r"(a2), "r"(a3), "r"(bv.z), "r"(bv.w));
        }
        if (kc + 1 < 32) *(uint4*)wd[(kc + 1) & 1] = pref;   // STS after MMAs
        __syncthreads();
    }

    // epilogue: lane holds rows m0, m0+8; cols tg*2, tg*2+1 per 8-wide n-tile
    const unsigned mk = (unsigned)(k0 + m0);
#pragma unroll
    for (int nt = 0; nt < 16; nt++) {
        unsigned long long key0 = packkey(d[nt*4+0], mk);
        unsigned long long u2 = packkey(d[nt*4+2], mk + 8); if (u2 > key0) key0 = u2;
        unsigned long long key1 = packkey(d[nt*4+1], mk);
        unsigned long long u3 = packkey(d[nt*4+3], mk + 8); if (u3 > key1) key1 = u3;
#pragma unroll
        for (int s = 4; s <= 16; s <<= 1) {     // reduce over g (lane bits 2..4)
            unsigned long long o0 = __shfl_xor_sync(0xFFFFFFFFu, key0, s); if (o0 > key0) key0 = o0;
            unsigned long long o1 = __shfl_xor_sync(0xFFFFFFFFu, key1, s); if (o1 > key1) key1 = o1;
        }
        if (lid < 4) {                          // lid == tg here
            red[wid * 128 + nt * 8 + lid * 2]     = key0;
            red[wid * 128 + nt * 8 + lid * 2 + 1] = key1;
        }
    }
    __syncthreads();
    if (tid < 128) {
        unsigned long long m = red[tid];
#pragma unroll
        for (int w = 1; w < 8; w++) {
            unsigned long long o = red[w * 128 + tid];
            if (o > m) m = o;
        }
        if (tid < FF) d_ckey[(b * FF + tid) * NCHK2 + tile] = m;
    }
}

// ==== candidate selection: per frame, emit chunks within 3.0 of gmax ====
__global__ __launch_bounds__(256) void k_csel() {
    __shared__ unsigned long long keys[NCHK2];
    __shared__ float thr;
    const int tid = threadIdx.x;
    const int bf = blockIdx.x;
    keys[tid] = d_ckey[bf * NCHK2 + tid];
    __syncthreads();
    if (tid == 0) {
        unsigned long long g = keys[0];
        for (int c = 1; c < NCHK2; c++) if (keys[c] > g) g = keys[c];
        thr = unpackval(g) - 3.0f;   // > 2x deterministic bf16 error bound
    }
    __syncthreads();
    if (unpackval(keys[tid]) >= thr) {
        int pos = atomicAdd(&d_njobs, 1);
        d_jobs[pos] = (unsigned)(bf * NCHK2 + tid);
    }
}

// ==== STAGE 2: exact fp32 recompute, one block per candidate chunk ====
__global__ __launch_bounds__(128) void k_cand2(const float* __restrict__ recon,
                                               const float* __restrict__ target) {
    __shared__ __align__(16) float wsh[512];
    __shared__ float xs[640];
    __shared__ unsigned long long wred[4];
    const int tid = threadIdx.x;
    const int njobs = d_njobs;

    for (int ji = blockIdx.x; ji < njobs; ji += gridDim.x) {
        const unsigned v = d_jobs[ji];
        const int bf = (int)(v >> 8), chunk = (int)(v & 255u);
        const int b = bf / FF, f = bf % FF;
        const int k0 = chunk * 128;
        const float* tb = target + b * NN;
        const float* rb = recon + b * NN + f * 256;

        __syncthreads();   // protect smem reuse across jobs
        for (int j = tid; j < 512; j += 128) wsh[j] = hamm(j) * rb[j];
        for (int i = tid; i < 640; i += 128) {
            int gi = k0 - 512 + i;
            xs[i] = (gi >= 0) ? tb[gi] : 0.0f;
        }
        __syncthreads();

        float acc = 0.0f;
        const float* xp = xs + tid + 512;
#pragma unroll 8
        for (int j0 = 0; j0 < 512; j0 += 4) {   // j ascending, one fma per j: exact chain
            float4 wv = *(const float4*)(wsh + j0);
            acc = fmaf(wv.x, xp[-j0], acc);
            acc = fmaf(wv.y, xp[-j0 - 1], acc);
            acc = fmaf(wv.z, xp[-j0 - 2], acc);
            acc = fmaf(wv.w, xp[-j0 - 3], acc);
        }
        unsigned long long key = packkey(acc, (unsigned)(k0 + tid));
#pragma unroll
        for (int s = 16; s > 0; s >>= 1) {
            unsigned long long o = __shfl_xor_sync(0xFFFFFFFFu, key, s);
            if (o > key) key = o;
        }
        if ((tid & 31) == 0) wred[tid >> 5] = key;
        __syncthreads();
        if (tid == 0) {
            unsigned long long m = wred[0];
            if (wred[1] > m) m = wred[1];
            if (wred[2] > m) m = wred[2];
            if (wred[3] > m) m = wred[3];
            atomicMax(&d_amax[bf], m);
        }
    }
}

// ---- per-frame params + moments for the far-field expansion ----
__global__ void k_prep(const float* __restrict__ recon) {
    __shared__ float4 red[128];
    const int bf = blockIdx.x;
    const int b = bf / FF, f = bf % FF;
    const int tid = threadIdx.x;
    const unsigned a = 0xFFFFFFFFu - (unsigned)(d_amax[bf] & 0xFFFFFFFFull);
    const bool delta = (a == 0u);
    const float r = (float)a * (1.0f / 32769.0f);
    const float beta = delta ? 1.0f
        : ((a & 1u) ? -1.0f : 1.0f) * sinpif(r) * (1.0f / 65536.0f);
    const float* rb = recon + b * NN + f * 256;

    float m0 = 0.f, m1 = 0.f, m2 = 0.f, m3 = 0.f;
#pragma unroll
    for (int q = 0; q < 4; q++) {
        int j = tid * 4 + q;
        float s = (j & 1) ? -1.0f : 1.0f;
        float g = beta * s * hamm(j) * rb[j];
        float tau = (255.5f - (float)j) * (1.0f / 256.0f);
        float t2 = tau * tau;
        m0 += g; m1 += g * tau; m2 += g * t2; m3 += g * t2 * tau;
    }
    red[tid] = make_float4(m0, m1, m2, m3);
    __syncthreads();
    for (int s = 64; s > 0; s >>= 1) {
        if (tid < s) {
            float4 x = red[tid], y = red[tid + s];
            red[tid] = make_float4(x.x+y.x, x.y+y.y, x.z+y.z, x.w+y.w);
        }
        __syncthreads();
    }
    if (tid == 0) {
        float* e = d_ftab + bf * 8;
        float4 m = red[0];
        e[0] = __int_as_float((int)a);
        e[1] = r;
        e[2] = m.x; e[3] = m.y; e[4] = m.z; e[5] = m.w;
    }
}

// one far-field eval (cubic cot-Taylor x moments)
#define FAR_EVAL(kk) do { \
    float u = (dbase + (float)(kk)) * (1.0f / 65536.0f); \
    float c0 = __fdividef(cospif(u), sinpif(u)); \
    float c2 = c0 * c0; \
    float q = c2 + 1.0f; \
    float t = fmaf(G, fmaf(G, (c2 + 0.33333333f) * M3, -c0 * M2), M1); \
    F[kk] = fmaf(c0, M0, fmaf(-G * q, t, F[kk])); \
} while (0)

// ---- far-field: frame-chunked; hoisted near-band classification ----
__global__ __launch_bounds__(256) void k_far() {
    __shared__ float ft[FCH * 8];
    const int tid = threadIdx.x;
    const int chunk = blockIdx.y, b = blockIdx.z;
    const int f0 = chunk * FCH;
    const int nf = (f0 + FCH < FF) ? FCH : (FF - f0);
    for (int i = tid; i < nf * 8; i += 256) ft[i] = d_ftab[(b * FF + f0) * 8 + i];
    __syncthreads();

    const int m0i = blockIdx.x * 1024 + tid * 4;
    float F[4] = {0.f, 0.f, 0.f, 0.f};
    const float G = 0.01227184630f;   // pi/256

    for (int f = 0; f < nf; f++) {
        const float* e = ft + f * 8;
        int a = __float_as_int(e[0]);
        if (a == 0) continue;                      // delta frame: fully in near band
        float r = e[1], M0 = e[2], M1 = e[3], M2 = e[4], M3 = e[5];
        float dbase = (float)(m0i - a) + (r - 255.5f);
        int rel = m0i - (a - NEAR_LO);
        if (rel + 3 < 0 || rel >= NEAR_SPAN) {     // whole 4-vector outside band
            FAR_EVAL(0); FAR_EVAL(1); FAR_EVAL(2); FAR_EVAL(3);
        } else {
#pragma unroll
            for (int k = 0; k < 4; k++) {
                if ((unsigned)(rel + k) < (unsigned)NEAR_SPAN) continue;
                FAR_EVAL(k);
            }
        }
    }
    float4 outv = make_float4(F[0], -F[1], F[2], -F[3]);
    *(float4*)(d_Pc + ((size_t)(chunk * BB + b)) * NN + m0i) = outv;
}

// Register-sliding-window 512-tap fp32 conv (proven R5 structure)
__device__ __forceinline__ void conv16(const float* __restrict__ csh,
                                       const float* __restrict__ wsh,
                                       int tid, float* __restrict__ acc) {
    float X[24];
    const float* base = csh + 16 * tid + 504;
#pragma unroll
    for (int i = 0; i < 6; i++) {
        float4 v = *(const float4*)(base + 4 * i);
        X[4*i+0]=v.x; X[4*i+1]=v.y; X[4*i+2]=v.z; X[4*i+3]=v.w;
    }
#pragma unroll 8
    for (int j0 = 0; j0 < 512; j0 += 8) {
        float4 w0 = *(const float4*)(wsh + j0);
        float4 w1 = *(const float4*)(wsh + j0 + 4);
        float wr[8] = {w0.x,w0.y,w0.z,w0.w,w1.x,w1.y,w1.z,w1.w};
#pragma unroll
        for (int c = 0; c < 8; c++)
#pragma unroll
            for (int t = 0; t < 16; t++)
                acc[t] = fmaf(wr[c], X[8 + t - c], acc[t]);
#pragma unroll
        for (int i = 23; i >= 8; i--) X[i] = X[i - 8];
        float4 n0 = *(const float4*)(base - j0 - 8);
        float4 n1 = *(const float4*)(base - j0 - 4);
        X[0]=n0.x; X[1]=n0.y; X[2]=n0.z; X[3]=n0.w;
        X[4]=n1.x; X[5]=n1.y; X[6]=n1.z; X[7]=n1.w;
    }
}

// ---- near-field: exact 512-tap conv, 2 blocks x 2048 outputs per frame ----
__global__ __launch_bounds__(128, 4) void k_near(const float* __restrict__ recon) {
    __shared__ __align__(16) float raw[2592];
    __shared__ __align__(16) float wsh[512];
    float* csh = raw + 8;
    const int tid = threadIdx.x;
    const int f = blockIdx.y, b = blockIdx.z;
    const int bf = b * FF + f;
    const unsigned a = 0xFFFFFFFFu - (unsigned)(d_amax[bf] & 0xFFFFFFFFull);
    const int tile0 = (int)a - NEAR_LO + blockIdx.x * 2048;
    if (tile0 >= NN || tile0 + 2048 <= 0) return;
    const bool delta = (a == 0u);
    const float r = (float)a * (1.0f / 32769.0f);
    const float beta = delta ? 1.0f
        : ((a & 1u) ? -1.0f : 1.0f) * sinpif(r) * (1.0f / 65536.0f);
    const float* rb = recon + b * NN + f * 256;

    for (int j = tid; j < 512; j += 128) {
        float s = (j & 1) ? -1.0f : 1.0f;
        wsh[j] = beta * s * hamm(j) * rb[j];
    }
    for (int i = tid; i < 2592; i += 128) {
        int d = tile0 - 520 + i;
        float v;
        if (delta) {
            v = (d == 0) ? 1.0f : 0.0f;
        } else if (d < -511) {
            v = 0.0f;
        } else {
            float u = ((float)(d - (int)a) + r) * (1.0f / 65536.0f);
            v = __fdividef(cospif(u), sinpif(u));
        }
        raw[i] = v;
    }
    __syncthreads();

    float acc[16];
#pragma unroll
    for (int t = 0; t < 16; t++) acc[t] = 0.0f;
    conv16(csh, wsh, tid, acc);

    const int mb = tile0 + 16 * tid;
    float* Pb = d_Pc + b * NN;
#pragma unroll
    for (int t = 0; t < 16; t++) {
        int m = mb + t;
        if ((unsigned)m < (unsigned)NN) {
            float val = (m & 1) ? -acc[t] : acc[t];
            atomicAdd(Pb + m, val);
        }
    }
}

// ---- parallel MSE reduction ----
__global__ void k_loss(const float* __restrict__ target) {
    __shared__ double red[256];
    const int tid = threadIdx.x;
    double s = 0.0;
    for (int i = blockIdx.x * 256 + tid; i < BB * NN; i += gridDim.x * 256) {
        int b = i >> 15, m = i & (NN - 1);
        float p = 0.f;
#pragma unroll
        for (int c = 0; c < NCH; c++)
            p += d_Pc[((size_t)(c * BB + b)) * NN + m];
        double dd = (double)p - (double)target[i];
        s += dd * dd;
    }
    red[tid] = s;
    __syncthreads();
    for (int st = 128; st > 0; st >>= 1) {
        if (tid < st) red[tid] += red[tid + st];
        __syncthreads();
    }
    if (tid == 0) atomicAdd(&d_acc, red[0]);
}

__global__ void k_final(float* __restrict__ out) {
    out[0] = (float)(d_acc / (double)(BB * NN));
}

extern "C" void kernel_launch(void* const* d_in, const int* in_sizes, int n_in,
                              void* d_out, int out_size) {
    const float* recon  = (const float*)d_in[0];
    const float* target = (const float*)d_in[1];
    float* out = (float*)d_out;
    (void)in_sizes; (void)n_in; (void)out_size;

    k_wprep<<<BB * 128, 128>>>(recon);
    k_s1t<<<dim3(NN / 128, BB), 256>>>(target);
    k_csel<<<NFT, 256>>>();
    k_cand2<<<1024, 128>>>(recon, target);
    k_prep<<<NFT, 128>>>(recon);
    k_far<<<dim3(NN / 1024, NCH, BB), 256>>>();
    k_near<<<dim3(2, FF, BB), 128>>>(recon);
    k_loss<<<128, 256>>>(target);
    k_final<<<1, 1>>>(out);
}

// round 15
// speedup vs baseline: 3.5147x; 1.0327x over previous
#include <cuda_runtime.h>
#include <cuda_bf16.h>

#define NN 32768
#define BB 4
#define WW 512
#define FF 127
#define NFT (BB*FF)
#define NEAR_LO 1792
#define NEAR_SPAN 4096
#define FCH 16            // frames per far-chunk
#define NCH 8             // far chunks
#define NCHK2 256         // 128-wide argmax chunks per row
#define MAXJOBS (NFT * NCHK2)

// dynamic smem layout for k_s1t
#define S1_WALL 0               // 32768 u32 = 128 KB (all B chunks)
#define S1_TREV 131072          // 640 u16
#define S1_RED  132352          // 1024 u64 = 8 KB
#define S1_SMEM 140544

// ---- device scratch ----
__device__ unsigned long long d_amax[NFT];
__device__ unsigned long long d_ckey[NFT * NCHK2];   // stage-1 per-chunk max keys
__device__ unsigned d_wbf[BB * 32 * 1024];           // fragment-ordered bf16 weights
__device__ unsigned d_jobs[MAXJOBS];
__device__ int d_njobs;
__device__ float d_Pc[NCH * BB * NN];
__device__ float d_ftab[NFT * 8];
__device__ double d_acc;

__device__ __forceinline__ float hamm(int j) {
    return 0.54f - 0.46f * cospif((float)j * (1.0f / 256.0f));
}

// order-preserving pack; ties -> smaller k wins (matches jnp.argmax)
__device__ __forceinline__ unsigned long long packkey(float v, unsigned k) {
    unsigned u = __float_as_uint(v);
    u = (u & 0x80000000u) ? ~u : (u | 0x80000000u);
    return ((unsigned long long)u << 32) | (0xFFFFFFFFu - k);
}
__device__ __forceinline__ float unpackval(unsigned long long key) {
    unsigned uv = (unsigned)(key >> 32);
    unsigned u = (uv & 0x80000000u) ? (uv & 0x7FFFFFFFu) : ~uv;
    return __uint_as_float(u);
}

// ---- weight prep (fragment-ordered, swizzled) + global init ----
__global__ __launch_bounds__(128) void k_wprep(const float* __restrict__ recon) {
    const int bn = blockIdx.x;            // b*128 + n
    const int b = bn >> 7, n = bn & 127;
    const int tid = threadIdx.x;

    if (bn == 0) {
        for (int i = tid; i < NFT; i += 128) d_amax[i] = 0ull;
        if (tid == 0) { d_acc = 0.0; d_njobs = 0; }
    }

    const int j = tid * 4;
    float w0 = 0.f, w1 = 0.f, w2 = 0.f, w3 = 0.f;
    if (n < FF) {
        const float* rb = recon + b * NN + n * 256;
        w0 = hamm(j) * rb[j];     w1 = hamm(j+1) * rb[j+1];
        w2 = hamm(j+2) * rb[j+2]; w3 = hamm(j+3) * rb[j+3];
    }
    unsigned lo = (unsigned)__bfloat16_as_ushort(__float2bfloat16(w0))
                | ((unsigned)__bfloat16_as_ushort(__float2bfloat16(w1)) << 16);
    unsigned hi = (unsigned)__bfloat16_as_ushort(__float2bfloat16(w2))
                | ((unsigned)__bfloat16_as_ushort(__float2bfloat16(w3)) << 16);

    const int g = n & 7, nt = n >> 3, p = nt >> 1;
    const int sbase = (nt & 1) * 2;
#pragma unroll
    for (int q = 0; q < 2; q++) {
        const int ku = tid * 2 + q;
        const int kc = ku >> 3, cc = ku & 7;
        const int tg = cc & 3, half = cc >> 2;
        const int c = g * 4 + tg;
        const int flat = (((b * 32 + kc) * 32 + c) * 32) + (((p + c) & 7) * 4) + sbase + half;
        d_wbf[flat] = q ? hi : lo;
    }
}

// ==== STAGE 1: tensor-core conv1, ALL B chunks resident in smem, no inner syncs ====
__global__ __launch_bounds__(256) void k_s1t(const float* __restrict__ target) {
    extern __shared__ char sm[];
    unsigned* wall = (unsigned*)(sm + S1_WALL);
    unsigned short* trev = (unsigned short*)(sm + S1_TREV);
    unsigned long long* red = (unsigned long long*)(sm + S1_RED);

    const int tid = threadIdx.x;
    const int wid = tid >> 5, lid = tid & 31;
    const int g = lid >> 2, tg = lid & 3;
    const int tile = blockIdx.x, b = blockIdx.y;
    const int k0 = tile * 128;
    const float* tb = target + b * NN;

    // load ALL 32 B chunks (128 KB) with full MLP
    const uint4* wsrc4 = (const uint4*)(d_wbf + b * 32768);
    uint4* wall4 = (uint4*)wall;
#pragma unroll
    for (int r = 0; r < 32; r++) wall4[tid + r * 256] = wsrc4[tid + r * 256];

    for (int i = tid; i < 640; i += 256) {
        int gi = k0 + 127 - i;
        float v = (gi >= 0) ? tb[gi] : 0.0f;
        trev[i] = __bfloat16_as_ushort(__float2bfloat16(v));
    }
    __syncthreads();

    float d[64];
#pragma unroll
    for (int i = 0; i < 64; i++) d[i] = 0.0f;

    const int m0 = 16 * wid + g;

    for (int kc = 0; kc < 32; kc++) {
        const unsigned* wc = wall + kc * 1024 + lid * 32;
        const int i0 = 127 - m0 + kc * 16 + tg * 2;
        unsigned a0 = (unsigned)trev[i0]     | ((unsigned)trev[i0 + 1] << 16);
        unsigned a1 = (unsigned)trev[i0 - 8] | ((unsigned)trev[i0 - 7] << 16);
        unsigned a2 = (unsigned)trev[i0 + 8] | ((unsigned)trev[i0 + 9] << 16);
        unsigned a3 = a0;   // Toeplitz: row+8, col+8 -> same data
#pragma unroll
        for (int p = 0; p < 8; p++) {
            uint4 bv = *(const uint4*)(wc + (((p + lid) & 7) << 2));
            float* d0 = d + (2 * p) * 4;
            float* d1 = d + (2 * p + 1) * 4;
            asm volatile(
                "mma.sync.aligned.m16n8k16.row.col.f32.bf16.bf16.f32 "
                "{%0,%1,%2,%3}, {%4,%5,%6,%7}, {%8,%9}, {%0,%1,%2,%3};"
                : "+f"(d0[0]), "+f"(d0[1]), "+f"(d0[2]), "+f"(d0[3])
                : "r"(a0), "r"(a1), "r"(a2), "r"(a3), "r"(bv.x), "r"(bv.y));
            asm volatile(
                "mma.sync.aligned.m16n8k16.row.col.f32.bf16.bf16.f32 "
                "{%0,%1,%2,%3}, {%4,%5,%6,%7}, {%8,%9}, {%0,%1,%2,%3};"
                : "+f"(d1[0]), "+f"(d1[1]), "+f"(d1[2]), "+f"(d1[3])
                : "r"(a0), "r"(a1), "r"(a2), "r"(a3), "r"(bv.z), "r"(bv.w));
        }
    }

    // epilogue: lane holds rows m0, m0+8; cols tg*2, tg*2+1 per 8-wide n-tile
    const unsigned mk = (unsigned)(k0 + m0);
#pragma unroll
    for (int nt = 0; nt < 16; nt++) {
        unsigned long long key0 = packkey(d[nt*4+0], mk);
        unsigned long long u2 = packkey(d[nt*4+2], mk + 8); if (u2 > key0) key0 = u2;
        unsigned long long key1 = packkey(d[nt*4+1], mk);
        unsigned long long u3 = packkey(d[nt*4+3], mk + 8); if (u3 > key1) key1 = u3;
#pragma unroll
        for (int s = 4; s <= 16; s <<= 1) {     // reduce over g (lane bits 2..4)
            unsigned long long o0 = __shfl_xor_sync(0xFFFFFFFFu, key0, s); if (o0 > key0) key0 = o0;
            unsigned long long o1 = __shfl_xor_sync(0xFFFFFFFFu, key1, s); if (o1 > key1) key1 = o1;
        }
        if (lid < 4) {                          // lid == tg here
            red[wid * 128 + nt * 8 + lid * 2]     = key0;
            red[wid * 128 + nt * 8 + lid * 2 + 1] = key1;
        }
    }
    __syncthreads();
    if (tid < 128) {
        unsigned long long m = red[tid];
#pragma unroll
        for (int w = 1; w < 8; w++) {
            unsigned long long o = red[w * 128 + tid];
            if (o > m) m = o;
        }
        if (tid < FF) d_ckey[(b * FF + tid) * NCHK2 + tile] = m;
    }
}

// ==== candidate selection: per frame, emit chunks within 3.0 of gmax ====
__global__ __launch_bounds__(256) void k_csel() {
    __shared__ unsigned long long keys[NCHK2];
    __shared__ float thr;
    const int tid = threadIdx.x;
    const int bf = blockIdx.x;
    keys[tid] = d_ckey[bf * NCHK2 + tid];
    __syncthreads();
    if (tid == 0) {
        unsigned long long g = keys[0];
        for (int c = 1; c < NCHK2; c++) if (keys[c] > g) g = keys[c];
        thr = unpackval(g) - 3.0f;   // > 2x deterministic bf16 error bound
    }
    __syncthreads();
    if (unpackval(keys[tid]) >= thr) {
        int pos = atomicAdd(&d_njobs, 1);
        d_jobs[pos] = (unsigned)(bf * NCHK2 + tid);
    }
}

// ==== STAGE 2: exact fp32 recompute, ONE JOB PER WARP, 4 outputs/lane (ILP-4) ====
__global__ __launch_bounds__(256) void k_cand2(const float* __restrict__ recon,
                                               const float* __restrict__ target) {
    __shared__ __align__(16) float wsh[8][512];
    __shared__ __align__(16) float xs[8][640];
    const int tid = threadIdx.x;
    const int wid = tid >> 5, lane = tid & 31;
    const int njobs = d_njobs;

    for (int ji = blockIdx.x * 8 + wid; ji < njobs; ji += gridDim.x * 8) {
        const unsigned v = d_jobs[ji];
        const int bf = (int)(v >> 8), chunk = (int)(v & 255u);
        const int b = bf / FF, f = bf % FF;
        const int k0 = chunk * 128;
        const float* tb = target + b * NN;
        const float* rb = recon + b * NN + f * 256;
        float* w = wsh[wid];
        float* x = xs[wid];

        for (int j = lane; j < 512; j += 32) w[j] = hamm(j) * rb[j];
        for (int i = lane; i < 640; i += 32) {
            int gi = k0 - 512 + i;
            x[i] = (gi >= 0) ? tb[gi] : 0.0f;
        }
        __syncwarp();

        float acc[4] = {0.f, 0.f, 0.f, 0.f};
        const float* xp = x + 512 + lane;
#pragma unroll 4
        for (int j0 = 0; j0 < 512; j0 += 4) {   // per-output: j ascending, 1 fma/j (exact chain)
            float4 wv = *(const float4*)(w + j0);
#pragma unroll
            for (int q = 0; q < 4; q++) {
                const float* p = xp + 32 * q - j0;
                acc[q] = fmaf(wv.x, p[0],  acc[q]);
                acc[q] = fmaf(wv.y, p[-1], acc[q]);
                acc[q] = fmaf(wv.z, p[-2], acc[q]);
                acc[q] = fmaf(wv.w, p[-3], acc[q]);
            }
        }
        unsigned long long key = packkey(acc[0], (unsigned)(k0 + lane));
#pragma unroll
        for (int q = 1; q < 4; q++) {
            unsigned long long kq = packkey(acc[q], (unsigned)(k0 + lane + 32 * q));
            if (kq > key) key = kq;
        }
#pragma unroll
        for (int s = 16; s > 0; s >>= 1) {
            unsigned long long o = __shfl_xor_sync(0xFFFFFFFFu, key, s);
            if (o > key) key = o;
        }
        if (lane == 0) atomicMax(&d_amax[bf], key);
        __syncwarp();   // done with w/x before next job overwrites
    }
}

// ---- per-frame params + moments for the far-field expansion ----
__global__ void k_prep(const float* __restrict__ recon) {
    __shared__ float4 red[128];
    const int bf = blockIdx.x;
    const int b = bf / FF, f = bf % FF;
    const int tid = threadIdx.x;
    const unsigned a = 0xFFFFFFFFu - (unsigned)(d_amax[bf] & 0xFFFFFFFFull);
    const bool delta = (a == 0u);
    const float r = (float)a * (1.0f / 32769.0f);
    const float beta = delta ? 1.0f
        : ((a & 1u) ? -1.0f : 1.0f) * sinpif(r) * (1.0f / 65536.0f);
    const float* rb = recon + b * NN + f * 256;

    float m0 = 0.f, m1 = 0.f, m2 = 0.f, m3 = 0.f;
#pragma unroll
    for (int q = 0; q < 4; q++) {
        int j = tid * 4 + q;
        float s = (j & 1) ? -1.0f : 1.0f;
        float g = beta * s * hamm(j) * rb[j];
        float tau = (255.5f - (float)j) * (1.0f / 256.0f);
        float t2 = tau * tau;
        m0 += g; m1 += g * tau; m2 += g * t2; m3 += g * t2 * tau;
    }
    red[tid] = make_float4(m0, m1, m2, m3);
    __syncthreads();
    for (int s = 64; s > 0; s >>= 1) {
        if (tid < s) {
            float4 x = red[tid], y = red[tid + s];
            red[tid] = make_float4(x.x+y.x, x.y+y.y, x.z+y.z, x.w+y.w);
        }
        __syncthreads();
    }
    if (tid == 0) {
        float* e = d_ftab + bf * 8;
        float4 m = red[0];
        e[0] = __int_as_float((int)a);
        e[1] = r;
        e[2] = m.x; e[3] = m.y; e[4] = m.z; e[5] = m.w;
    }
}

// one far-field eval (cubic cot-Taylor x moments)
#define FAR_EVAL(kk) do { \
    float u = (dbase + (float)(kk)) * (1.0f / 65536.0f); \
    float c0 = __fdividef(cospif(u), sinpif(u)); \
    float c2 = c0 * c0; \
    float q = c2 + 1.0f; \
    float t = fmaf(G, fmaf(G, (c2 + 0.33333333f) * M3, -c0 * M2), M1); \
    F[kk] = fmaf(c0, M0, fmaf(-G * q, t, F[kk])); \
} while (0)

// ---- far-field: frame-chunked; hoisted near-band classification ----
__global__ __launch_bounds__(256) void k_far() {
    __shared__ float ft[FCH * 8];
    const int tid = threadIdx.x;
    const int chunk = blockIdx.y, b = blockIdx.z;
    const int f0 = chunk * FCH;
    const int nf = (f0 + FCH < FF) ? FCH : (FF - f0);
    for (int i = tid; i < nf * 8; i += 256) ft[i] = d_ftab[(b * FF + f0) * 8 + i];
    __syncthreads();

    const int m0i = blockIdx.x * 1024 + tid * 4;
    float F[4] = {0.f, 0.f, 0.f, 0.f};
    const float G = 0.01227184630f;   // pi/256

    for (int f = 0; f < nf; f++) {
        const float* e = ft + f * 8;
        int a = __float_as_int(e[0]);
        if (a == 0) continue;                      // delta frame: fully in near band
        float r = e[1], M0 = e[2], M1 = e[3], M2 = e[4], M3 = e[5];
        float dbase = (float)(m0i - a) + (r - 255.5f);
        int rel = m0i - (a - NEAR_LO);
        if (rel + 3 < 0 || rel >= NEAR_SPAN) {
            FAR_EVAL(0); FAR_EVAL(1); FAR_EVAL(2); FAR_EVAL(3);
        } else {
#pragma unroll
            for (int k = 0; k < 4; k++) {
                if ((unsigned)(rel + k) < (unsigned)NEAR_SPAN) continue;
                FAR_EVAL(k);
            }
        }
    }
    float4 outv = make_float4(F[0], -F[1], F[2], -F[3]);
    *(float4*)(d_Pc + ((size_t)(chunk * BB + b)) * NN + m0i) = outv;
}

// Register-sliding-window 512-tap fp32 conv (proven R5 structure)
__device__ __forceinline__ void conv16(const float* __restrict__ csh,
                                       const float* __restrict__ wsh,
                                       int tid, float* __restrict__ acc) {
    float X[24];
    const float* base = csh + 16 * tid + 504;
#pragma unroll
    for (int i = 0; i < 6; i++) {
        float4 v = *(const float4*)(base + 4 * i);
        X[4*i+0]=v.x; X[4*i+1]=v.y; X[4*i+2]=v.z; X[4*i+3]=v.w;
    }
#pragma unroll 8
    for (int j0 = 0; j0 < 512; j0 += 8) {
        float4 w0 = *(const float4*)(wsh + j0);
        float4 w1 = *(const float4*)(wsh + j0 + 4);
        float wr[8] = {w0.x,w0.y,w0.z,w0.w,w1.x,w1.y,w1.z,w1.w};
#pragma unroll
        for (int c = 0; c < 8; c++)
#pragma unroll
            for (int t = 0; t < 16; t++)
                acc[t] = fmaf(wr[c], X[8 + t - c], acc[t]);
#pragma unroll
        for (int i = 23; i >= 8; i--) X[i] = X[i - 8];
        float4 n0 = *(const float4*)(base - j0 - 8);
        float4 n1 = *(const float4*)(base - j0 - 4);
        X[0]=n0.x; X[1]=n0.y; X[2]=n0.z; X[3]=n0.w;
        X[4]=n1.x; X[5]=n1.y; X[6]=n1.z; X[7]=n1.w;
    }
}

// ---- near-field: exact 512-tap conv, 2 blocks x 2048 outputs per frame ----
__global__ __launch_bounds__(128, 4) void k_near(const float* __restrict__ recon) {
    __shared__ __align__(16) float raw[2592];
    __shared__ __align__(16) float wsh[512];
    float* csh = raw + 8;
    const int tid = threadIdx.x;
    const int f = blockIdx.y, b = blockIdx.z;
    const int bf = b * FF + f;
    const unsigned a = 0xFFFFFFFFu - (unsigned)(d_amax[bf] & 0xFFFFFFFFull);
    const int tile0 = (int)a - NEAR_LO + blockIdx.x * 2048;
    if (tile0 >= NN || tile0 + 2048 <= 0) return;
    const bool delta = (a == 0u);
    const float r = (float)a * (1.0f / 32769.0f);
    const float beta = delta ? 1.0f
        : ((a & 1u) ? -1.0f : 1.0f) * sinpif(r) * (1.0f / 65536.0f);
    const float* rb = recon + b * NN + f * 256;

    for (int j = tid; j < 512; j += 128) {
        float s = (j & 1) ? -1.0f : 1.0f;
        wsh[j] = beta * s * hamm(j) * rb[j];
    }
    for (int i = tid; i < 2592; i += 128) {
        int d = tile0 - 520 + i;
        float v;
        if (delta) {
            v = (d == 0) ? 1.0f : 0.0f;
        } else if (d < -511) {
            v = 0.0f;
        } else {
            float u = ((float)(d - (int)a) + r) * (1.0f / 65536.0f);
            v = __fdividef(cospif(u), sinpif(u));
        }
        raw[i] = v;
    }
    __syncthreads();

    float acc[16];
#pragma unroll
    for (int t = 0; t < 16; t++) acc[t] = 0.0f;
    conv16(csh, wsh, tid, acc);

    const int mb = tile0 + 16 * tid;
    float* Pb = d_Pc + b * NN;
#pragma unroll
    for (int t = 0; t < 16; t++) {
        int m = mb + t;
        if ((unsigned)m < (unsigned)NN) {
            float val = (m & 1) ? -acc[t] : acc[t];
            atomicAdd(Pb + m, val);
        }
    }
}

// ---- parallel MSE reduction ----
__global__ void k_loss(const float* __restrict__ target) {
    __shared__ double red[256];
    const int tid = threadIdx.x;
    double s = 0.0;
    for (int i = blockIdx.x * 256 + tid; i < BB * NN; i += gridDim.x * 256) {
        int b = i >> 15, m = i & (NN - 1);
        float p = 0.f;
#pragma unroll
        for (int c = 0; c < NCH; c++)
            p += d_Pc[((size_t)(c * BB + b)) * NN + m];
        double dd = (double)p - (double)target[i];
        s += dd * dd;
    }
    red[tid] = s;
    __syncthreads();
    for (int st = 128; st > 0; st >>= 1) {
        if (tid < st) red[tid] += red[tid + st];
        __syncthreads();
    }
    if (tid == 0) atomicAdd(&d_acc, red[0]);
}

__global__ void k_final(float* __restrict__ out) {
    out[0] = (float)(d_acc / (double)(BB * NN));
}

extern "C" void kernel_launch(void* const* d_in, const int* in_sizes, int n_in,
                              void* d_out, int out_size) {
    const float* recon  = (const float*)d_in[0];
    const float* target = (const float*)d_in[1];
    float* out = (float*)d_out;
    (void)in_sizes; (void)n_in; (void)out_size;

    cudaFuncSetAttribute(k_s1t, cudaFuncAttributeMaxDynamicSharedMemorySize, S1_SMEM);

    k_wprep<<<BB * 128, 128>>>(recon);
    k_s1t<<<dim3(NN / 128, BB), 256, S1_SMEM>>>(target);
    k_csel<<<NFT, 256>>>();
    k_cand2<<<256, 256>>>(recon, target);
    k_prep<<<NFT, 128>>>(recon);
    k_far<<<dim3(NN / 1024, NCH, BB), 256>>>();
    k_near<<<dim3(2, FF, BB), 128>>>(recon);
    k_loss<<<128, 256>>>(target);
    k_final<<<1, 1>>>(out);
}

// round 16
// speedup vs baseline: 3.5612x; 1.0132x over previous
#include <cuda_runtime.h>
#include <cuda_bf16.h>

#define NN 32768
#define BB 4
#define WW 512
#define FF 127
#define NFT (BB*FF)
#define NEAR_LO 1792
#define NEAR_SPAN 4096
#define FCH 16            // frames per far-chunk
#define NCH 8             // far chunks
#define NCHP 9            // partial buffers: 8 far + 1 near
#define NCHK2 256         // 128-wide argmax chunks per row
#define MAXJOBS (NFT * NCHK2)
#define NFARBLK 1024      // 32 m-tiles x 8 chunks x 4 b

// dynamic smem layout for k_s1t
#define S1_WALL 0               // 32768 u32 = 128 KB (all B chunks)
#define S1_TREV 131072          // 640 u16
#define S1_RED  132352          // 1024 u64 = 8 KB
#define S1_SMEM 140544

// ---- device scratch ----
__device__ unsigned long long d_amax[NFT];
__device__ unsigned long long d_ckey[NFT * NCHK2];   // stage-1 per-chunk max keys
__device__ unsigned d_wbf[BB * 32 * 1024];           // fragment-ordered bf16 weights
__device__ unsigned d_jobs[MAXJOBS];
__device__ int d_njobs;
__device__ float d_Pc[NCHP * BB * NN];
__device__ float d_ftab[NFT * 8];
__device__ double d_acc;

__device__ __forceinline__ float hamm(int j) {
    return 0.54f - 0.46f * cospif((float)j * (1.0f / 256.0f));
}

// order-preserving pack; ties -> smaller k wins (matches jnp.argmax)
__device__ __forceinline__ unsigned long long packkey(float v, unsigned k) {
    unsigned u = __float_as_uint(v);
    u = (u & 0x80000000u) ? ~u : (u | 0x80000000u);
    return ((unsigned long long)u << 32) | (0xFFFFFFFFu - k);
}
__device__ __forceinline__ float unpackval(unsigned long long key) {
    unsigned uv = (unsigned)(key >> 32);
    unsigned u = (uv & 0x80000000u) ? (uv & 0x7FFFFFFFu) : ~uv;
    return __uint_as_float(u);
}

// ---- weight prep (fragment-ordered, swizzled) + per-call global init ----
__global__ __launch_bounds__(128) void k_wprep(const float* __restrict__ recon) {
    const int bn = blockIdx.x;            // b*128 + n
    const int b = bn >> 7, n = bn & 127;
    const int tid = threadIdx.x;

    if (bn == 0) {
        for (int i = tid; i < NFT; i += 128) d_amax[i] = 0ull;
        if (tid == 0) { d_acc = 0.0; d_njobs = 0; }
    }
    // zero the near partial slot (graph replays need this every call)
    {
        float* pn = d_Pc + (size_t)(8 * BB) * NN;
        const int per = (BB * NN) / (BB * 128);   // 256 floats per block
        int base = bn * per;
        for (int i = tid; i < per; i += 128) pn[base + i] = 0.0f;
    }

    const int j = tid * 4;
    float w0 = 0.f, w1 = 0.f, w2 = 0.f, w3 = 0.f;
    if (n < FF) {
        const float* rb = recon + b * NN + n * 256;
        w0 = hamm(j) * rb[j];     w1 = hamm(j+1) * rb[j+1];
        w2 = hamm(j+2) * rb[j+2]; w3 = hamm(j+3) * rb[j+3];
    }
    unsigned lo = (unsigned)__bfloat16_as_ushort(__float2bfloat16(w0))
                | ((unsigned)__bfloat16_as_ushort(__float2bfloat16(w1)) << 16);
    unsigned hi = (unsigned)__bfloat16_as_ushort(__float2bfloat16(w2))
                | ((unsigned)__bfloat16_as_ushort(__float2bfloat16(w3)) << 16);

    const int g = n & 7, nt = n >> 3, p = nt >> 1;
    const int sbase = (nt & 1) * 2;
#pragma unroll
    for (int q = 0; q < 2; q++) {
        const int ku = tid * 2 + q;
        const int kc = ku >> 3, cc = ku & 7;
        const int tg = cc & 3, half = cc >> 2;
        const int c = g * 4 + tg;
        const int flat = (((b * 32 + kc) * 32 + c) * 32) + (((p + c) & 7) * 4) + sbase + half;
        d_wbf[flat] = q ? hi : lo;
    }
}

// ==== STAGE 1: tensor-core conv1, ALL B chunks resident in smem, no inner syncs ====
__global__ __launch_bounds__(256) void k_s1t(const float* __restrict__ target) {
    extern __shared__ char sm[];
    unsigned* wall = (unsigned*)(sm + S1_WALL);
    unsigned short* trev = (unsigned short*)(sm + S1_TREV);
    unsigned long long* red = (unsigned long long*)(sm + S1_RED);

    const int tid = threadIdx.x;
    const int wid = tid >> 5, lid = tid & 31;
    const int g = lid >> 2, tg = lid & 3;
    const int tile = blockIdx.x, b = blockIdx.y;
    const int k0 = tile * 128;
    const float* tb = target + b * NN;

    const uint4* wsrc4 = (const uint4*)(d_wbf + b * 32768);
    uint4* wall4 = (uint4*)wall;
#pragma unroll
    for (int r = 0; r < 32; r++) wall4[tid + r * 256] = wsrc4[tid + r * 256];

    for (int i = tid; i < 640; i += 256) {
        int gi = k0 + 127 - i;
        float v = (gi >= 0) ? tb[gi] : 0.0f;
        trev[i] = __bfloat16_as_ushort(__float2bfloat16(v));
    }
    __syncthreads();

    float d[64];
#pragma unroll
    for (int i = 0; i < 64; i++) d[i] = 0.0f;

    const int m0 = 16 * wid + g;

    for (int kc = 0; kc < 32; kc++) {
        const unsigned* wc = wall + kc * 1024 + lid * 32;
        const int i0 = 127 - m0 + kc * 16 + tg * 2;
        unsigned a0 = (unsigned)trev[i0]     | ((unsigned)trev[i0 + 1] << 16);
        unsigned a1 = (unsigned)trev[i0 - 8] | ((unsigned)trev[i0 - 7] << 16);
        unsigned a2 = (unsigned)trev[i0 + 8] | ((unsigned)trev[i0 + 9] << 16);
        unsigned a3 = a0;   // Toeplitz: row+8, col+8 -> same data
#pragma unroll
        for (int p = 0; p < 8; p++) {
            uint4 bv = *(const uint4*)(wc + (((p + lid) & 7) << 2));
            float* d0 = d + (2 * p) * 4;
            float* d1 = d + (2 * p + 1) * 4;
            asm volatile(
                "mma.sync.aligned.m16n8k16.row.col.f32.bf16.bf16.f32 "
                "{%0,%1,%2,%3}, {%4,%5,%6,%7}, {%8,%9}, {%0,%1,%2,%3};"
                : "+f"(d0[0]), "+f"(d0[1]), "+f"(d0[2]), "+f"(d0[3])
                : "r"(a0), "r"(a1), "r"(a2), "r"(a3), "r"(bv.x), "r"(bv.y));
            asm volatile(
                "mma.sync.aligned.m16n8k16.row.col.f32.bf16.bf16.f32 "
                "{%0,%1,%2,%3}, {%4,%5,%6,%7}, {%8,%9}, {%0,%1,%2,%3};"
                : "+f"(d1[0]), "+f"(d1[1]), "+f"(d1[2]), "+f"(d1[3])
                : "r"(a0), "r"(a1), "r"(a2), "r"(a3), "r"(bv.z), "r"(bv.w));
        }
    }

    const unsigned mk = (unsigned)(k0 + m0);
#pragma unroll
    for (int nt = 0; nt < 16; nt++) {
        unsigned long long key0 = packkey(d[nt*4+0], mk);
        unsigned long long u2 = packkey(d[nt*4+2], mk + 8); if (u2 > key0) key0 = u2;
        unsigned long long key1 = packkey(d[nt*4+1], mk);
        unsigned long long u3 = packkey(d[nt*4+3], mk + 8); if (u3 > key1) key1 = u3;
#pragma unroll
        for (int s = 4; s <= 16; s <<= 1) {
            unsigned long long o0 = __shfl_xor_sync(0xFFFFFFFFu, key0, s); if (o0 > key0) key0 = o0;
            unsigned long long o1 = __shfl_xor_sync(0xFFFFFFFFu, key1, s); if (o1 > key1) key1 = o1;
        }
        if (lid < 4) {
            red[wid * 128 + nt * 8 + lid * 2]     = key0;
            red[wid * 128 + nt * 8 + lid * 2 + 1] = key1;
        }
    }
    __syncthreads();
    if (tid < 128) {
        unsigned long long m = red[tid];
#pragma unroll
        for (int w = 1; w < 8; w++) {
            unsigned long long o = red[w * 128 + tid];
            if (o > m) m = o;
        }
        if (tid < FF) d_ckey[(b * FF + tid) * NCHK2 + tile] = m;
    }
}

// ==== candidate selection: per frame, emit chunks within 3.0 of gmax ====
__global__ __launch_bounds__(256) void k_csel() {
    __shared__ unsigned long long keys[NCHK2];
    __shared__ float thr;
    const int tid = threadIdx.x;
    const int bf = blockIdx.x;
    keys[tid] = d_ckey[bf * NCHK2 + tid];
    __syncthreads();
    if (tid == 0) {
        unsigned long long g = keys[0];
        for (int c = 1; c < NCHK2; c++) if (keys[c] > g) g = keys[c];
        thr = unpackval(g) - 3.0f;   // > 2x deterministic bf16 error bound
    }
    __syncthreads();
    if (unpackval(keys[tid]) >= thr) {
        int pos = atomicAdd(&d_njobs, 1);
        d_jobs[pos] = (unsigned)(bf * NCHK2 + tid);
    }
}

// ==== STAGE 2: exact fp32 recompute, one block per candidate chunk (R14 form) ====
__global__ __launch_bounds__(128) void k_cand2(const float* __restrict__ recon,
                                               const float* __restrict__ target) {
    __shared__ __align__(16) float wsh[512];
    __shared__ float xs[640];
    __shared__ unsigned long long wred[4];
    const int tid = threadIdx.x;
    const int njobs = d_njobs;

    for (int ji = blockIdx.x; ji < njobs; ji += gridDim.x) {
        const unsigned v = d_jobs[ji];
        const int bf = (int)(v >> 8), chunk = (int)(v & 255u);
        const int b = bf / FF, f = bf % FF;
        const int k0 = chunk * 128;
        const float* tb = target + b * NN;
        const float* rb = recon + b * NN + f * 256;

        __syncthreads();
        for (int j = tid; j < 512; j += 128) wsh[j] = hamm(j) * rb[j];
        for (int i = tid; i < 640; i += 128) {
            int gi = k0 - 512 + i;
            xs[i] = (gi >= 0) ? tb[gi] : 0.0f;
        }
        __syncthreads();

        float acc = 0.0f;
        const float* xp = xs + tid + 512;
#pragma unroll 8
        for (int j0 = 0; j0 < 512; j0 += 4) {   // j ascending, one fma per j: exact chain
            float4 wv = *(const float4*)(wsh + j0);
            acc = fmaf(wv.x, xp[-j0], acc);
            acc = fmaf(wv.y, xp[-j0 - 1], acc);
            acc = fmaf(wv.z, xp[-j0 - 2], acc);
            acc = fmaf(wv.w, xp[-j0 - 3], acc);
        }
        unsigned long long key = packkey(acc, (unsigned)(k0 + tid));
#pragma unroll
        for (int s = 16; s > 0; s >>= 1) {
            unsigned long long o = __shfl_xor_sync(0xFFFFFFFFu, key, s);
            if (o > key) key = o;
        }
        if ((tid & 31) == 0) wred[tid >> 5] = key;
        __syncthreads();
        if (tid == 0) {
            unsigned long long m = wred[0];
            if (wred[1] > m) m = wred[1];
            if (wred[2] > m) m = wred[2];
            if (wred[3] > m) m = wred[3];
            atomicMax(&d_amax[bf], m);
        }
    }
}

// ---- per-frame params + moments for the far-field expansion ----
__global__ void k_prep(const float* __restrict__ recon) {
    __shared__ float4 red[128];
    const int bf = blockIdx.x;
    const int b = bf / FF, f = bf % FF;
    const int tid = threadIdx.x;
    const unsigned a = 0xFFFFFFFFu - (unsigned)(d_amax[bf] & 0xFFFFFFFFull);
    const bool delta = (a == 0u);
    const float r = (float)a * (1.0f / 32769.0f);
    const float beta = delta ? 1.0f
        : ((a & 1u) ? -1.0f : 1.0f) * sinpif(r) * (1.0f / 65536.0f);
    const float* rb = recon + b * NN + f * 256;

    float m0 = 0.f, m1 = 0.f, m2 = 0.f, m3 = 0.f;
#pragma unroll
    for (int q = 0; q < 4; q++) {
        int j = tid * 4 + q;
        float s = (j & 1) ? -1.0f : 1.0f;
        float g = beta * s * hamm(j) * rb[j];
        float tau = (255.5f - (float)j) * (1.0f / 256.0f);
        float t2 = tau * tau;
        m0 += g; m1 += g * tau; m2 += g * t2; m3 += g * t2 * tau;
    }
    red[tid] = make_float4(m0, m1, m2, m3);
    __syncthreads();
    for (int s = 64; s > 0; s >>= 1) {
        if (tid < s) {
            float4 x = red[tid], y = red[tid + s];
            red[tid] = make_float4(x.x+y.x, x.y+y.y, x.z+y.z, x.w+y.w);
        }
        __syncthreads();
    }
    if (tid == 0) {
        float* e = d_ftab + bf * 8;
        float4 m = red[0];
        e[0] = __int_as_float((int)a);
        e[1] = r;
        e[2] = m.x; e[3] = m.y; e[4] = m.z; e[5] = m.w;
    }
}

// one far-field eval (cubic cot-Taylor x moments)
#define FAR_EVAL(kk) do { \
    float u = (dbase + (float)(kk)) * (1.0f / 65536.0f); \
    float c0 = __fdividef(cospif(u), sinpif(u)); \
    float c2 = c0 * c0; \
    float q = c2 + 1.0f; \
    float t = fmaf(G, fmaf(G, (c2 + 0.33333333f) * M3, -c0 * M2), M1); \
    F[kk] = fmaf(c0, M0, fmaf(-G * q, t, F[kk])); \
} while (0)

// Register-sliding-window 512-tap fp32 conv (proven R5 structure)
__device__ __forceinline__ void conv16(const float* __restrict__ csh,
                                       const float* __restrict__ wsh,
                                       int tid, float* __restrict__ acc) {
    float X[24];
    const float* base = csh + 16 * tid + 504;
#pragma unroll
    for (int i = 0; i < 6; i++) {
        float4 v = *(const float4*)(base + 4 * i);
        X[4*i+0]=v.x; X[4*i+1]=v.y; X[4*i+2]=v.z; X[4*i+3]=v.w;
    }
#pragma unroll 8
    for (int j0 = 0; j0 < 512; j0 += 8) {
        float4 w0 = *(const float4*)(wsh + j0);
        float4 w1 = *(const float4*)(wsh + j0 + 4);
        float wr[8] = {w0.x,w0.y,w0.z,w0.w,w1.x,w1.y,w1.z,w1.w};
#pragma unroll
        for (int c = 0; c < 8; c++)
#pragma unroll
            for (int t = 0; t < 16; t++)
                acc[t] = fmaf(wr[c], X[8 + t - c], acc[t]);
#pragma unroll
        for (int i = 23; i >= 8; i--) X[i] = X[i - 8];
        float4 n0 = *(const float4*)(base - j0 - 8);
        float4 n1 = *(const float4*)(base - j0 - 4);
        X[0]=n0.x; X[1]=n0.y; X[2]=n0.z; X[3]=n0.w;
        X[4]=n1.x; X[5]=n1.y; X[6]=n1.z; X[7]=n1.w;
    }
}

// ==== FUSED far + near: blocks [0,1024) far, [1024,1532) near ====
// far writes d_Pc slots 0..7; near atomicAdds into slot 8 (pre-zeroed in wprep).
__global__ __launch_bounds__(256) void k_fn(const float* __restrict__ recon) {
    __shared__ __align__(16) float sh[4640 + 512];
    const int tid = threadIdx.x;

    if (blockIdx.x < NFARBLK) {
        // ---------- FAR ----------
        float* ft = sh;                          // FCH*8 = 128 floats
        const int fid = blockIdx.x;
        const int mt = fid & 31;
        const int chunk = (fid >> 5) & 7;
        const int b = fid >> 8;
        const int f0 = chunk * FCH;
        const int nf = (f0 + FCH < FF) ? FCH : (FF - f0);
        for (int i = tid; i < nf * 8; i += 256) ft[i] = d_ftab[(b * FF + f0) * 8 + i];
        __syncthreads();

        const int m0i = mt * 1024 + tid * 4;
        float F[4] = {0.f, 0.f, 0.f, 0.f};
        const float G = 0.01227184630f;          // pi/256

        for (int f = 0; f < nf; f++) {
            const float* e = ft + f * 8;
            int a = __float_as_int(e[0]);
            if (a == 0) continue;                // delta frame: fully in near band
            float r = e[1], M0 = e[2], M1 = e[3], M2 = e[4], M3 = e[5];
            float dbase = (float)(m0i - a) + (r - 255.5f);
            int rel = m0i - (a - NEAR_LO);
            if (rel + 3 < 0 || rel >= NEAR_SPAN) {
                FAR_EVAL(0); FAR_EVAL(1); FAR_EVAL(2); FAR_EVAL(3);
            } else {
#pragma unroll
                for (int k = 0; k < 4; k++) {
                    if ((unsigned)(rel + k) < (unsigned)NEAR_SPAN) continue;
                    FAR_EVAL(k);
                }
            }
        }
        float4 outv = make_float4(F[0], -F[1], F[2], -F[3]);
        *(float4*)(d_Pc + ((size_t)(chunk * BB + b)) * NN + m0i) = outv;
    } else {
        // ---------- NEAR (exact 512-tap conv over the 4096 band) ----------
        float* raw = sh;
        float* wsh = sh + 4640;
        float* csh = raw + 16;
        const int nid = blockIdx.x - NFARBLK;
        const int f = nid % FF, b = nid / FF;
        const int bf = b * FF + f;
        const unsigned a = 0xFFFFFFFFu - (unsigned)(d_amax[bf] & 0xFFFFFFFFull);
        const int tile0 = (int)a - NEAR_LO;
        const bool delta = (a == 0u);
        const float r = (float)a * (1.0f / 32769.0f);
        const float beta = delta ? 1.0f
            : ((a & 1u) ? -1.0f : 1.0f) * sinpif(r) * (1.0f / 65536.0f);
        const float* rb = recon + b * NN + f * 256;

        for (int j = tid; j < 512; j += 256) {
            float s = (j & 1) ? -1.0f : 1.0f;
            wsh[j] = beta * s * hamm(j) * rb[j];
        }
        for (int i = tid; i < 4624; i += 256) {
            int d = tile0 - 528 + i;
            float v;
            if (delta) {
                v = (d == 0) ? 1.0f : 0.0f;
            } else if (d < -511) {
                v = 0.0f;
            } else {
                float u = ((float)(d - (int)a) + r) * (1.0f / 65536.0f);
                v = __fdividef(cospif(u), sinpif(u));
            }
            raw[i] = v;
        }
        __syncthreads();

        float acc[16];
#pragma unroll
        for (int t = 0; t < 16; t++) acc[t] = 0.0f;
        conv16(csh, wsh, tid, acc);

        const int mb = tile0 + 16 * tid;
        float* Pb = d_Pc + ((size_t)(8 * BB) + b) * NN;   // near slot
#pragma unroll
        for (int t = 0; t < 16; t++) {
            int m = mb + t;
            if ((unsigned)m < (unsigned)NN) {
                float val = (m & 1) ? -acc[t] : acc[t];
                atomicAdd(Pb + m, val);
            }
        }
    }
}

// ---- parallel MSE reduction over 9 partials ----
__global__ void k_loss(const float* __restrict__ target) {
    __shared__ double red[256];
    const int tid = threadIdx.x;
    double s = 0.0;
    for (int i = blockIdx.x * 256 + tid; i < BB * NN; i += gridDim.x * 256) {
        int b = i >> 15, m = i & (NN - 1);
        float p = 0.f;
#pragma unroll
        for (int c = 0; c < NCHP; c++)
            p += d_Pc[((size_t)(c * BB + b)) * NN + m];
        double dd = (double)p - (double)target[i];
        s += dd * dd;
    }
    red[tid] = s;
    __syncthreads();
    for (int st = 128; st > 0; st >>= 1) {
        if (tid < st) red[tid] += red[tid + st];
        __syncthreads();
    }
    if (tid == 0) atomicAdd(&d_acc, red[0]);
}

__global__ void k_final(float* __restrict__ out) {
    out[0] = (float)(d_acc / (double)(BB * NN));
}

extern "C" void kernel_launch(void* const* d_in, const int* in_sizes, int n_in,
                              void* d_out, int out_size) {
    const float* recon  = (const float*)d_in[0];
    const float* target = (const float*)d_in[1];
    float* out = (float*)d_out;
    (void)in_sizes; (void)n_in; (void)out_size;

    cudaFuncSetAttribute(k_s1t, cudaFuncAttributeMaxDynamicSharedMemorySize, S1_SMEM);

    k_wprep<<<BB * 128, 128>>>(recon);
    k_s1t<<<dim3(NN / 128, BB), 256, S1_SMEM>>>(target);
    k_csel<<<NFT, 256>>>();
    k_cand2<<<1024, 128>>>(recon, target);
    k_prep<<<NFT, 128>>>(recon);
    k_fn<<<NFARBLK + NFT, 256>>>(recon);
    k_loss<<<128, 256>>>(target);
    k_final<<<1, 1>>>(out);
}

// round 17
// speedup vs baseline: 3.6888x; 1.0358x over previous
#include <cuda_runtime.h>
#include <cuda_bf16.h>

#define NN 32768
#define BB 4
#define WW 512
#define FF 127
#define NFT (BB*FF)
#define NEAR_LO 1792
#define NEAR_SPAN 4096
#define FCH 16            // frames per far-chunk
#define NCH 8             // far chunks
#define NCHP 9            // partial buffers: 8 far + 1 near
#define NCHK2 256         // 128-wide argmax chunks per row
#define MAXJOBS (NFT * NCHK2)
#define NFARBLK 1024      // 32 m-tiles x 8 chunks x 4 b

// dynamic smem layout for k_s1t (half-frame CTAs)
#define S1_WALL 0               // 16384 u32 = 64 KB (one frame-half's B chunks)
#define S1_TREV 65536           // 640 u16
#define S1_RED  66816           // 512 u64 = 4 KB
#define S1_SMEM 70912

// ---- device scratch ----
__device__ unsigned long long d_amax[NFT];
__device__ unsigned long long d_ckey[NFT * NCHK2];   // stage-1 per-chunk max keys
__device__ unsigned d_wbf[BB * 2 * 16384];           // fragment-ordered bf16 weights [b][nh]...
__device__ unsigned d_jobs[MAXJOBS];
__device__ int d_njobs;
__device__ float d_Pc[NCHP * BB * NN];
__device__ float d_ftab[NFT * 8];
__device__ double d_acc;

__device__ __forceinline__ float hamm(int j) {
    return 0.54f - 0.46f * cospif((float)j * (1.0f / 256.0f));
}

// order-preserving pack; ties -> smaller k wins (matches jnp.argmax)
__device__ __forceinline__ unsigned long long packkey(float v, unsigned k) {
    unsigned u = __float_as_uint(v);
    u = (u & 0x80000000u) ? ~u : (u | 0x80000000u);
    return ((unsigned long long)u << 32) | (0xFFFFFFFFu - k);
}
__device__ __forceinline__ float unpackval(unsigned long long key) {
    unsigned uv = (unsigned)(key >> 32);
    unsigned u = (uv & 0x80000000u) ? (uv & 0x7FFFFFFFu) : ~uv;
    return __uint_as_float(u);
}

// 4-slot swizzle: lanes c, c+1, c+2, c+4 all map to different slots
__device__ __forceinline__ int swz4(int p, int c) {
    return (p + c + (c >> 2)) & 3;
}

// ---- weight prep (half-split fragment layout) + per-call global init ----
// frame n: nh=n>>6, nt_local=(n>>3)&7, p_local=nt_local>>1, s0=(nt_local&1)*2, g=n&7.
// k u32 ku: kc=ku>>3, tg=(ku&7)&3, khalf=(ku&7)>>2. class c=g*4+tg.
// flat = ((((b*2+nh)*32+kc)*32+c)*16) + swz4(p_local,c)*4 + s0 + khalf.
__global__ __launch_bounds__(128) void k_wprep(const float* __restrict__ recon) {
    const int bn = blockIdx.x;            // b*128 + n
    const int b = bn >> 7, n = bn & 127;
    const int tid = threadIdx.x;

    if (bn == 0) {
        for (int i = tid; i < NFT; i += 128) d_amax[i] = 0ull;
        if (tid == 0) { d_acc = 0.0; d_njobs = 0; }
    }
    // zero the near partial slot (graph replays need this every call)
    {
        float* pn = d_Pc + (size_t)(8 * BB) * NN;
        const int per = 256;
        int base = bn * per;
        for (int i = tid; i < per; i += 128) pn[base + i] = 0.0f;
    }

    const int j = tid * 4;
    float w0 = 0.f, w1 = 0.f, w2 = 0.f, w3 = 0.f;
    if (n < FF) {
        const float* rb = recon + b * NN + n * 256;
        w0 = hamm(j) * rb[j];     w1 = hamm(j+1) * rb[j+1];
        w2 = hamm(j+2) * rb[j+2]; w3 = hamm(j+3) * rb[j+3];
    }
    unsigned lo = (unsigned)__bfloat16_as_ushort(__float2bfloat16(w0))
                | ((unsigned)__bfloat16_as_ushort(__float2bfloat16(w1)) << 16);
    unsigned hi = (unsigned)__bfloat16_as_ushort(__float2bfloat16(w2))
                | ((unsigned)__bfloat16_as_ushort(__float2bfloat16(w3)) << 16);

    const int g = n & 7;
    const int nh = n >> 6;
    const int nt_local = (n >> 3) & 7;
    const int pl = nt_local >> 1;
    const int s0 = (nt_local & 1) * 2;
#pragma unroll
    for (int q = 0; q < 2; q++) {
        const int ku = tid * 2 + q;
        const int kc = ku >> 3, cc = ku & 7;
        const int tg = cc & 3, khalf = cc >> 2;
        const int c = g * 4 + tg;
        const int flat = ((((b * 2 + nh) * 32 + kc) * 32 + c) * 16)
                       + swz4(pl, c) * 4 + s0 + khalf;
        d_wbf[flat] = q ? hi : lo;
    }
}

// ==== STAGE 1: tensor-core conv1, per-CTA = (128-kpos tile, frame-half, batch) ====
__global__ __launch_bounds__(256) void k_s1t(const float* __restrict__ target) {
    extern __shared__ char sm[];
    unsigned* wall = (unsigned*)(sm + S1_WALL);
    unsigned short* trev = (unsigned short*)(sm + S1_TREV);
    unsigned long long* red = (unsigned long long*)(sm + S1_RED);

    const int tid = threadIdx.x;
    const int wid = tid >> 5, lid = tid & 31;
    const int g = lid >> 2, tg = lid & 3;
    const int tile = blockIdx.x, nh = blockIdx.y, b = blockIdx.z;
    const int k0 = tile * 128;
    const float* tb = target + b * NN;

    // load this half's B wall (64 KB) with full MLP
    const uint4* wsrc4 = (const uint4*)(d_wbf + (b * 2 + nh) * 16384);
    uint4* wall4 = (uint4*)wall;
#pragma unroll
    for (int r = 0; r < 16; r++) wall4[tid + r * 256] = wsrc4[tid + r * 256];

    for (int i = tid; i < 640; i += 256) {
        int gi = k0 + 127 - i;
        float v = (gi >= 0) ? tb[gi] : 0.0f;
        trev[i] = __bfloat16_as_ushort(__float2bfloat16(v));
    }
    __syncthreads();

    float d[32];
#pragma unroll
    for (int i = 0; i < 32; i++) d[i] = 0.0f;

    const int m0 = 16 * wid + g;

    for (int kc = 0; kc < 32; kc++) {
        const unsigned* wc = wall + kc * 512 + lid * 16;
        const int i0 = 127 - m0 + kc * 16 + tg * 2;
        unsigned a0 = (unsigned)trev[i0]     | ((unsigned)trev[i0 + 1] << 16);
        unsigned a1 = (unsigned)trev[i0 - 8] | ((unsigned)trev[i0 - 7] << 16);
        unsigned a2 = (unsigned)trev[i0 + 8] | ((unsigned)trev[i0 + 9] << 16);
        unsigned a3 = a0;   // Toeplitz: row+8, col+8 -> same data
#pragma unroll
        for (int pl = 0; pl < 4; pl++) {
            uint4 bv = *(const uint4*)(wc + (swz4(pl, lid) << 2));
            float* d0 = d + (2 * pl) * 4;
            float* d1 = d + (2 * pl + 1) * 4;
            asm volatile(
                "mma.sync.aligned.m16n8k16.row.col.f32.bf16.bf16.f32 "
                "{%0,%1,%2,%3}, {%4,%5,%6,%7}, {%8,%9}, {%0,%1,%2,%3};"
                : "+f"(d0[0]), "+f"(d0[1]), "+f"(d0[2]), "+f"(d0[3])
                : "r"(a0), "r"(a1), "r"(a2), "r"(a3), "r"(bv.x), "r"(bv.y));
            asm volatile(
                "mma.sync.aligned.m16n8k16.row.col.f32.bf16.bf16.f32 "
                "{%0,%1,%2,%3}, {%4,%5,%6,%7}, {%8,%9}, {%0,%1,%2,%3};"
                : "+f"(d1[0]), "+f"(d1[1]), "+f"(d1[2]), "+f"(d1[3])
                : "r"(a0), "r"(a1), "r"(a2), "r"(a3), "r"(bv.z), "r"(bv.w));
        }
    }

    // epilogue: lane holds rows m0, m0+8; cols tg*2, tg*2+1 per local 8-wide n-tile
    const unsigned mk = (unsigned)(k0 + m0);
#pragma unroll
    for (int nt = 0; nt < 8; nt++) {
        unsigned long long key0 = packkey(d[nt*4+0], mk);
        unsigned long long u2 = packkey(d[nt*4+2], mk + 8); if (u2 > key0) key0 = u2;
        unsigned long long key1 = packkey(d[nt*4+1], mk);
        unsigned long long u3 = packkey(d[nt*4+3], mk + 8); if (u3 > key1) key1 = u3;
#pragma unroll
        for (int s = 4; s <= 16; s <<= 1) {     // reduce over g (lane bits 2..4)
            unsigned long long o0 = __shfl_xor_sync(0xFFFFFFFFu, key0, s); if (o0 > key0) key0 = o0;
            unsigned long long o1 = __shfl_xor_sync(0xFFFFFFFFu, key1, s); if (o1 > key1) key1 = o1;
        }
        if (lid < 4) {                          // lid == tg here
            red[wid * 64 + nt * 8 + lid * 2]     = key0;
            red[wid * 64 + nt * 8 + lid * 2 + 1] = key1;
        }
    }
    __syncthreads();
    if (tid < 64) {
        unsigned long long m = red[tid];
#pragma unroll
        for (int w = 1; w < 8; w++) {
            unsigned long long o = red[w * 64 + tid];
            if (o > m) m = o;
        }
        const int fglob = nh * 64 + tid;
        if (fglob < FF) d_ckey[(b * FF + fglob) * NCHK2 + tile] = m;
    }
}

// ==== candidate selection: per frame, emit chunks within 3.0 of gmax ====
__global__ __launch_bounds__(256) void k_csel() {
    __shared__ unsigned long long keys[NCHK2];
    __shared__ float thr;
    const int tid = threadIdx.x;
    const int bf = blockIdx.x;
    keys[tid] = d_ckey[bf * NCHK2 + tid];
    __syncthreads();
    if (tid == 0) {
        unsigned long long g = keys[0];
        for (int c = 1; c < NCHK2; c++) if (keys[c] > g) g = keys[c];
        thr = unpackval(g) - 3.0f;   // > 2x deterministic bf16 error bound
    }
    __syncthreads();
    if (unpackval(keys[tid]) >= thr) {
        int pos = atomicAdd(&d_njobs, 1);
        d_jobs[pos] = (unsigned)(bf * NCHK2 + tid);
    }
}

// ==== STAGE 2: exact fp32 recompute, one block per candidate chunk ====
__global__ __launch_bounds__(128) void k_cand2(const float* __restrict__ recon,
                                               const float* __restrict__ target) {
    __shared__ __align__(16) float wsh[512];
    __shared__ float xs[640];
    __shared__ unsigned long long wred[4];
    const int tid = threadIdx.x;
    const int njobs = d_njobs;

    for (int ji = blockIdx.x; ji < njobs; ji += gridDim.x) {
        const unsigned v = d_jobs[ji];
        const int bf = (int)(v >> 8), chunk = (int)(v & 255u);
        const int b = bf / FF, f = bf % FF;
        const int k0 = chunk * 128;
        const float* tb = target + b * NN;
        const float* rb = recon + b * NN + f * 256;

        __syncthreads();
        for (int j = tid; j < 512; j += 128) wsh[j] = hamm(j) * rb[j];
        for (int i = tid; i < 640; i += 128) {
            int gi = k0 - 512 + i;
            xs[i] = (gi >= 0) ? tb[gi] : 0.0f;
        }
        __syncthreads();

        float acc = 0.0f;
        const float* xp = xs + tid + 512;
#pragma unroll 8
        for (int j0 = 0; j0 < 512; j0 += 4) {   // j ascending, one fma per j: exact chain
            float4 wv = *(const float4*)(wsh + j0);
            acc = fmaf(wv.x, xp[-j0], acc);
            acc = fmaf(wv.y, xp[-j0 - 1], acc);
            acc = fmaf(wv.z, xp[-j0 - 2], acc);
            acc = fmaf(wv.w, xp[-j0 - 3], acc);
        }
        unsigned long long key = packkey(acc, (unsigned)(k0 + tid));
#pragma unroll
        for (int s = 16; s > 0; s >>= 1) {
            unsigned long long o = __shfl_xor_sync(0xFFFFFFFFu, key, s);
            if (o > key) key = o;
        }
        if ((tid & 31) == 0) wred[tid >> 5] = key;
        __syncthreads();
        if (tid == 0) {
            unsigned long long m = wred[0];
            if (wred[1] > m) m = wred[1];
            if (wred[2] > m) m = wred[2];
            if (wred[3] > m) m = wred[3];
            atomicMax(&d_amax[bf], m);
        }
    }
}

// ---- per-frame params + moments for the far-field expansion ----
__global__ void k_prep(const float* __restrict__ recon) {
    __shared__ float4 red[128];
    const int bf = blockIdx.x;
    const int b = bf / FF, f = bf % FF;
    const int tid = threadIdx.x;
    const unsigned a = 0xFFFFFFFFu - (unsigned)(d_amax[bf] & 0xFFFFFFFFull);
    const bool delta = (a == 0u);
    const float r = (float)a * (1.0f / 32769.0f);
    const float beta = delta ? 1.0f
        : ((a & 1u) ? -1.0f : 1.0f) * sinpif(r) * (1.0f / 65536.0f);
    const float* rb = recon + b * NN + f * 256;

    float m0 = 0.f, m1 = 0.f, m2 = 0.f, m3 = 0.f;
#pragma unroll
    for (int q = 0; q < 4; q++) {
        int j = tid * 4 + q;
        float s = (j & 1) ? -1.0f : 1.0f;
        float g = beta * s * hamm(j) * rb[j];
        float tau = (255.5f - (float)j) * (1.0f / 256.0f);
        float t2 = tau * tau;
        m0 += g; m1 += g * tau; m2 += g * t2; m3 += g * t2 * tau;
    }
    red[tid] = make_float4(m0, m1, m2, m3);
    __syncthreads();
    for (int s = 64; s > 0; s >>= 1) {
        if (tid < s) {
            float4 x = red[tid], y = red[tid + s];
            red[tid] = make_float4(x.x+y.x, x.y+y.y, x.z+y.z, x.w+y.w);
        }
        __syncthreads();
    }
    if (tid == 0) {
        float* e = d_ftab + bf * 8;
        float4 m = red[0];
        e[0] = __int_as_float((int)a);
        e[1] = r;
        e[2] = m.x; e[3] = m.y; e[4] = m.z; e[5] = m.w;
    }
}

// one far-field eval (cubic cot-Taylor x moments)
#define FAR_EVAL(kk) do { \
    float u = (dbase + (float)(kk)) * (1.0f / 65536.0f); \
    float c0 = __fdividef(cospif(u), sinpif(u)); \
    float c2 = c0 * c0; \
    float q = c2 + 1.0f; \
    float t = fmaf(G, fmaf(G, (c2 + 0.33333333f) * M3, -c0 * M2), M1); \
    F[kk] = fmaf(c0, M0, fmaf(-G * q, t, F[kk])); \
} while (0)

// Register-sliding-window 512-tap fp32 conv (proven R5 structure)
__device__ __forceinline__ void conv16(const float* __restrict__ csh,
                                       const float* __restrict__ wsh,
                                       int tid, float* __restrict__ acc) {
    float X[24];
    const float* base = csh + 16 * tid + 504;
#pragma unroll
    for (int i = 0; i < 6; i++) {
        float4 v = *(const float4*)(base + 4 * i);
        X[4*i+0]=v.x; X[4*i+1]=v.y; X[4*i+2]=v.z; X[4*i+3]=v.w;
    }
#pragma unroll 8
    for (int j0 = 0; j0 < 512; j0 += 8) {
        float4 w0 = *(const float4*)(wsh + j0);
        float4 w1 = *(const float4*)(wsh + j0 + 4);
        float wr[8] = {w0.x,w0.y,w0.z,w0.w,w1.x,w1.y,w1.z,w1.w};
#pragma unroll
        for (int c = 0; c < 8; c++)
#pragma unroll
            for (int t = 0; t < 16; t++)
                acc[t] = fmaf(wr[c], X[8 + t - c], acc[t]);
#pragma unroll
        for (int i = 23; i >= 8; i--) X[i] = X[i - 8];
        float4 n0 = *(const float4*)(base - j0 - 8);
        float4 n1 = *(const float4*)(base - j0 - 4);
        X[0]=n0.x; X[1]=n0.y; X[2]=n0.z; X[3]=n0.w;
        X[4]=n1.x; X[5]=n1.y; X[6]=n1.z; X[7]=n1.w;
    }
}

// ==== FUSED far + near: blocks [0,1024) far, [1024,1532) near ====
__global__ __launch_bounds__(256) void k_fn(const float* __restrict__ recon) {
    __shared__ __align__(16) float sh[4640 + 512];
    const int tid = threadIdx.x;

    if (blockIdx.x < NFARBLK) {
        // ---------- FAR ----------
        float* ft = sh;
        const int fid = blockIdx.x;
        const int mt = fid & 31;
        const int chunk = (fid >> 5) & 7;
        const int b = fid >> 8;
        const int f0 = chunk * FCH;
        const int nf = (f0 + FCH < FF) ? FCH : (FF - f0);
        for (int i = tid; i < nf * 8; i += 256) ft[i] = d_ftab[(b * FF + f0) * 8 + i];
        __syncthreads();

        const int m0i = mt * 1024 + tid * 4;
        float F[4] = {0.f, 0.f, 0.f, 0.f};
        const float G = 0.01227184630f;          // pi/256

        for (int f = 0; f < nf; f++) {
            const float* e = ft + f * 8;
            int a = __float_as_int(e[0]);
            if (a == 0) continue;                // delta frame: fully in near band
            float r = e[1], M0 = e[2], M1 = e[3], M2 = e[4], M3 = e[5];
            float dbase = (float)(m0i - a) + (r - 255.5f);
            int rel = m0i - (a - NEAR_LO);
            if (rel + 3 < 0 || rel >= NEAR_SPAN) {
                FAR_EVAL(0); FAR_EVAL(1); FAR_EVAL(2); FAR_EVAL(3);
            } else {
#pragma unroll
                for (int k = 0; k < 4; k++) {
                    if ((unsigned)(rel + k) < (unsigned)NEAR_SPAN) continue;
                    FAR_EVAL(k);
                }
            }
        }
        float4 outv = make_float4(F[0], -F[1], F[2], -F[3]);
        *(float4*)(d_Pc + ((size_t)(chunk * BB + b)) * NN + m0i) = outv;
    } else {
        // ---------- NEAR (exact 512-tap conv over the 4096 band) ----------
        float* raw = sh;
        float* wsh = sh + 4640;
        float* csh = raw + 16;
        const int nid = blockIdx.x - NFARBLK;
        const int f = nid % FF, b = nid / FF;
        const int bf = b * FF + f;
        const unsigned a = 0xFFFFFFFFu - (unsigned)(d_amax[bf] & 0xFFFFFFFFull);
        const int tile0 = (int)a - NEAR_LO;
        const bool delta = (a == 0u);
        const float r = (float)a * (1.0f / 32769.0f);
        const float beta = delta ? 1.0f
            : ((a & 1u) ? -1.0f : 1.0f) * sinpif(r) * (1.0f / 65536.0f);
        const float* rb = recon + b * NN + f * 256;

        for (int j = tid; j < 512; j += 256) {
            float s = (j & 1) ? -1.0f : 1.0f;
            wsh[j] = beta * s * hamm(j) * rb[j];
        }
        for (int i = tid; i < 4624; i += 256) {
            int d = tile0 - 528 + i;
            float v;
            if (delta) {
                v = (d == 0) ? 1.0f : 0.0f;
            } else if (d < -511) {
                v = 0.0f;
            } else {
                float u = ((float)(d - (int)a) + r) * (1.0f / 65536.0f);
                v = __fdividef(cospif(u), sinpif(u));
            }
            raw[i] = v;
        }
        __syncthreads();

        float acc[16];
#pragma unroll
        for (int t = 0; t < 16; t++) acc[t] = 0.0f;
        conv16(csh, wsh, tid, acc);

        const int mb = tile0 + 16 * tid;
        float* Pb = d_Pc + ((size_t)(8 * BB) + b) * NN;   // near slot
#pragma unroll
        for (int t = 0; t < 16; t++) {
            int m = mb + t;
            if ((unsigned)m < (unsigned)NN) {
                float val = (m & 1) ? -acc[t] : acc[t];
                atomicAdd(Pb + m, val);
            }
        }
    }
}

// ---- parallel MSE reduction over 9 partials ----
__global__ void k_loss(const float* __restrict__ target) {
    __shared__ double red[256];
    const int tid = threadIdx.x;
    double s = 0.0;
    for (int i = blockIdx.x * 256 + tid; i < BB * NN; i += gridDim.x * 256) {
        int b = i >> 15, m = i & (NN - 1);
        float p = 0.f;
#pragma unroll
        for (int c = 0; c < NCHP; c++)
            p += d_Pc[((size_t)(c * BB + b)) * NN + m];
        double dd = (double)p - (double)target[i];
        s += dd * dd;
    }
    red[tid] = s;
    __syncthreads();
    for (int st = 128; st > 0; st >>= 1) {
        if (tid < st) red[tid] += red[tid + st];
        __syncthreads();
    }
    if (tid == 0) atomicAdd(&d_acc, red[0]);
}

__global__ void k_final(float* __restrict__ out) {
    out[0] = (float)(d_acc / (double)(BB * NN));
}

extern "C" void kernel_launch(void* const* d_in, const int* in_sizes, int n_in,
                              void* d_out, int out_size) {
    const float* recon  = (const float*)d_in[0];
    const float* target = (const float*)d_in[1];
    float* out = (float*)d_out;
    (void)in_sizes; (void)n_in; (void)out_size;

    cudaFuncSetAttribute(k_s1t, cudaFuncAttributeMaxDynamicSharedMemorySize, S1_SMEM);

    k_wprep<<<BB * 128, 128>>>(recon);
    k_s1t<<<dim3(NN / 128, 2, BB), 256, S1_SMEM>>>(target);
    k_csel<<<NFT, 256>>>();
    k_cand2<<<1024, 128>>>(recon, target);
    k_prep<<<NFT, 128>>>(recon);
    k_fn<<<NFARBLK + NFT, 256>>>(recon);
    k_loss<<<128, 256>>>(target);
    k_final<<<1, 1>>>(out);
}